// round 1
// baseline (speedup 1.0000x reference)
#include <cuda_runtime.h>
#include <math.h>
#include <stdint.h>

// Problem constants (Gemma2 attention layer)
#define B_ 4
#define S_ 2048
#define H_ 2048
#define NH_ 8
#define NKV_ 4
#define HD_ 256
#define WIN_ 1024
#define SCALE_ 0.0625f   // 256^-0.5

// Scratch (device globals — no allocation allowed)
__device__ float g_q[(size_t)B_ * S_ * NH_ * HD_];     // 67 MB
__device__ float g_k[(size_t)B_ * S_ * NKV_ * HD_];    // 33.5 MB
__device__ float g_v[(size_t)B_ * S_ * NKV_ * HD_];    // 33.5 MB
__device__ float g_attn[(size_t)B_ * S_ * NH_ * HD_];  // 67 MB

// ---------------------------------------------------------------------------
// SGEMM: C[M,N] = A[M,K] @ W[K,N] (+ bias), all row-major, fp32.
// 128x128 tile, K-step 8, 256 threads, 8x8 register blocking.
// M % 128 == 0, N % 128 == 0, K % 8 == 0 assumed (true for all calls).
// ---------------------------------------------------------------------------
__global__ __launch_bounds__(256) void sgemm128(
    const float* __restrict__ A, const float* __restrict__ W,
    const float* __restrict__ bias, float* __restrict__ C,
    int M, int N, int K)
{
    __shared__ float As[8][128];  // As[k][m]
    __shared__ float Bs[8][128];  // Bs[k][n]

    const int tid = threadIdx.x;
    const int tx = tid & 15;      // 0..15 -> n
    const int ty = tid >> 4;      // 0..15 -> m
    const int m0 = blockIdx.y * 128;
    const int n0 = blockIdx.x * 128;

    // Global load indices
    const int arow = tid >> 1;         // 0..127
    const int acol = (tid & 1) * 4;    // 0 or 4
    const int brow = tid >> 5;         // 0..7
    const int bcol = (tid & 31) * 4;   // 0..124

    const float* Aptr = A + (size_t)(m0 + arow) * K + acol;
    const float* Bptr = W + (size_t)brow * N + n0 + bcol;

    float acc[8][8];
#pragma unroll
    for (int i = 0; i < 8; i++)
#pragma unroll
        for (int j = 0; j < 8; j++) acc[i][j] = 0.f;

    for (int k0 = 0; k0 < K; k0 += 8) {
        float4 av = *(const float4*)(Aptr + k0);
        float4 bv = *(const float4*)(Bptr + (size_t)k0 * N);
        As[acol + 0][arow] = av.x;
        As[acol + 1][arow] = av.y;
        As[acol + 2][arow] = av.z;
        As[acol + 3][arow] = av.w;
        *(float4*)&Bs[brow][bcol] = bv;
        __syncthreads();

#pragma unroll
        for (int kk = 0; kk < 8; kk++) {
            float4 a0 = *(const float4*)&As[kk][ty * 8];
            float4 a1 = *(const float4*)&As[kk][ty * 8 + 4];
            float4 b0 = *(const float4*)&Bs[kk][tx * 8];
            float4 b1 = *(const float4*)&Bs[kk][tx * 8 + 4];
            float a[8] = {a0.x, a0.y, a0.z, a0.w, a1.x, a1.y, a1.z, a1.w};
            float b[8] = {b0.x, b0.y, b0.z, b0.w, b1.x, b1.y, b1.z, b1.w};
#pragma unroll
            for (int i = 0; i < 8; i++)
#pragma unroll
                for (int j = 0; j < 8; j++) acc[i][j] += a[i] * b[j];
        }
        __syncthreads();
    }

    // Epilogue
    float bb[8];
#pragma unroll
    for (int j = 0; j < 8; j++) bb[j] = bias ? bias[n0 + tx * 8 + j] : 0.f;
#pragma unroll
    for (int i = 0; i < 8; i++) {
        float* crow = C + (size_t)(m0 + ty * 8 + i) * N + n0 + tx * 8;
        float4 w0 = {acc[i][0] + bb[0], acc[i][1] + bb[1], acc[i][2] + bb[2], acc[i][3] + bb[3]};
        float4 w1 = {acc[i][4] + bb[4], acc[i][5] + bb[5], acc[i][6] + bb[6], acc[i][7] + bb[7]};
        *(float4*)(crow) = w0;
        *(float4*)(crow + 4) = w1;
    }
}

// ---------------------------------------------------------------------------
// RoPE (NeoX style) applied in-place to q (8 heads) and k (4 heads).
// One thread per (b, s, head, d<128) rotation pair.
// ---------------------------------------------------------------------------
__global__ void rope_kernel(float* __restrict__ q, float* __restrict__ k,
                            const int* __restrict__ positions)
{
    const int total = B_ * S_ * (NH_ + NKV_) * (HD_ / 2);
    int idx = blockIdx.x * blockDim.x + threadIdx.x;
    if (idx >= total) return;
    const int d = idx & 127;
    int r = idx >> 7;
    const int head = r % (NH_ + NKV_);
    const int bs = r / (NH_ + NKV_);
    const int pos = positions[bs];

    const float inv_freq = powf(10000.0f, -(float)d * (1.0f / 128.0f));
    const float fr = (float)pos * inv_freq;
    float sn, cs;
    sincosf(fr, &sn, &cs);

    float* base;
    if (head < NH_)
        base = q + ((size_t)bs * NH_ + head) * HD_;
    else
        base = k + ((size_t)bs * NKV_ + (head - NH_)) * HD_;

    const float x1 = base[d];
    const float x2 = base[d + 128];
    base[d]       = x1 * cs - x2 * sn;
    base[d + 128] = x2 * cs + x1 * sn;
}

// ---------------------------------------------------------------------------
// Sliding-window flash attention, fp32.
// Grid: (S/64, NH, B). Block: 256 threads (16x16).
// Per CTA: 64 queries of one (b,h); iterate K/V tiles of 64 within the window.
// Thread (ty,tx): score block 4x4 (rows ty*4+i, cols tx*4+j),
//                 output block 4x16 (rows ty*4+i, dims tx*16+jj).
// ---------------------------------------------------------------------------
#define QT_LD 68   // padded row length for transposed Q/K/P tiles

__global__ __launch_bounds__(256) void attn_kernel(
    const float* __restrict__ Qg, const float* __restrict__ Kg,
    const float* __restrict__ Vg, float* __restrict__ Og)
{
    extern __shared__ float sm[];
    float* Qt  = sm;                  // [256][68]  Qt[d][m]
    float* Kt  = Qt + 256 * QT_LD;    // [256][68]  Kt[d][n]
    float* Vs  = Kt + 256 * QT_LD;    // [64][256]  Vs[n][d]
    float* Pst = Vs + 64 * 256;       // [64][68]   Pst[n][m]

    const int tid = threadIdx.x;
    const int tx = tid & 15;
    const int ty = tid >> 4;
    const int q0 = blockIdx.x * 64;
    const int h = blockIdx.y;
    const int b = blockIdx.z;
    const int kvh = h >> 1;  // NH/NKV = 2

    // Load Q tile (transposed) : 64 rows x 256 dims
    for (int idx = tid; idx < 64 * 64; idx += 256) {
        int n = idx >> 6;
        int d = (idx & 63) * 4;
        size_t base = ((size_t)((b * S_ + q0 + n) * NH_ + h)) * HD_ + d;
        float4 v4 = *(const float4*)(Qg + base);
        Qt[(d + 0) * QT_LD + n] = v4.x;
        Qt[(d + 1) * QT_LD + n] = v4.y;
        Qt[(d + 2) * QT_LD + n] = v4.z;
        Qt[(d + 3) * QT_LD + n] = v4.w;
    }

    float o[4][16];
#pragma unroll
    for (int i = 0; i < 4; i++)
#pragma unroll
        for (int j = 0; j < 16; j++) o[i][j] = 0.f;

    float rmax[4], rsum[4];
#pragma unroll
    for (int i = 0; i < 4; i++) { rmax[i] = -1e30f; rsum[i] = 0.f; }

    int jlo = q0 - (WIN_ - 1);
    if (jlo < 0) jlo = 0;
    const int jt0 = (jlo / 64) * 64;

    for (int jt = jt0; jt <= q0; jt += 64) {
        __syncthreads();  // previous iter's Pst/Vs consumers done
        // Load K (transposed) and V tiles
        for (int idx = tid; idx < 64 * 64; idx += 256) {
            int n = idx >> 6;
            int d = (idx & 63) * 4;
            size_t base = ((size_t)((b * S_ + jt + n) * NKV_ + kvh)) * HD_ + d;
            float4 k4 = *(const float4*)(Kg + base);
            float4 v4 = *(const float4*)(Vg + base);
            Kt[(d + 0) * QT_LD + n] = k4.x;
            Kt[(d + 1) * QT_LD + n] = k4.y;
            Kt[(d + 2) * QT_LD + n] = k4.z;
            Kt[(d + 3) * QT_LD + n] = k4.w;
            *(float4*)&Vs[n * 256 + d] = v4;
        }
        __syncthreads();

        // Scores: S = Q @ K^T, 4x4 per thread
        float s[4][4];
#pragma unroll
        for (int i = 0; i < 4; i++)
#pragma unroll
            for (int j = 0; j < 4; j++) s[i][j] = 0.f;

        const float* qtp = Qt + ty * 4;
        const float* ktp = Kt + tx * 4;
#pragma unroll 4
        for (int k = 0; k < 256; k++) {
            float4 qa = *(const float4*)(qtp + k * QT_LD);
            float4 kb = *(const float4*)(ktp + k * QT_LD);
            float qv[4] = {qa.x, qa.y, qa.z, qa.w};
            float kv[4] = {kb.x, kb.y, kb.z, kb.w};
#pragma unroll
            for (int i = 0; i < 4; i++)
#pragma unroll
                for (int j = 0; j < 4; j++) s[i][j] += qv[i] * kv[j];
        }

        // Mask + scale
#pragma unroll
        for (int i = 0; i < 4; i++) {
            int qi = q0 + ty * 4 + i;
#pragma unroll
            for (int j = 0; j < 4; j++) {
                int kj = jt + tx * 4 + j;
                bool valid = (kj <= qi) && (kj > qi - WIN_);
                s[i][j] = valid ? s[i][j] * SCALE_ : -1e30f;
            }
        }

        // Online softmax per row; rows reduced across the 16 tx lanes
#pragma unroll
        for (int i = 0; i < 4; i++) {
            float tm = fmaxf(fmaxf(s[i][0], s[i][1]), fmaxf(s[i][2], s[i][3]));
#pragma unroll
            for (int off = 8; off >= 1; off >>= 1)
                tm = fmaxf(tm, __shfl_xor_sync(0xffffffffu, tm, off));
            float newmax = fmaxf(rmax[i], tm);
            float alpha = __expf(0.f);  // placeholder to keep compiler honest
            alpha = expf(rmax[i] - newmax);
            float p[4], psum = 0.f;
#pragma unroll
            for (int j = 0; j < 4; j++) {
                p[j] = (s[i][j] > -5e29f) ? expf(s[i][j] - newmax) : 0.f;
                psum += p[j];
            }
#pragma unroll
            for (int off = 8; off >= 1; off >>= 1)
                psum += __shfl_xor_sync(0xffffffffu, psum, off);
            rsum[i] = rsum[i] * alpha + psum;
            rmax[i] = newmax;
#pragma unroll
            for (int jj = 0; jj < 16; jj++) o[i][jj] *= alpha;
            // store p to Pst transposed: Pst[n][m]
#pragma unroll
            for (int j = 0; j < 4; j++)
                Pst[(tx * 4 + j) * QT_LD + ty * 4 + i] = p[j];
        }
        __syncthreads();

        // O += P @ V
#pragma unroll 2
        for (int n = 0; n < 64; n++) {
            float4 p4 = *(const float4*)&Pst[n * QT_LD + ty * 4];
            float pr[4] = {p4.x, p4.y, p4.z, p4.w};
            const float* vr = Vs + n * 256 + tx * 16;
            float4 v0 = *(const float4*)(vr);
            float4 v1 = *(const float4*)(vr + 4);
            float4 v2 = *(const float4*)(vr + 8);
            float4 v3 = *(const float4*)(vr + 12);
            float vv[16] = {v0.x, v0.y, v0.z, v0.w, v1.x, v1.y, v1.z, v1.w,
                            v2.x, v2.y, v2.z, v2.w, v3.x, v3.y, v3.z, v3.w};
#pragma unroll
            for (int i = 0; i < 4; i++)
#pragma unroll
                for (int jj = 0; jj < 16; jj++) o[i][jj] += pr[i] * vv[jj];
        }
    }

    // Finalize: divide by row sum, write out
#pragma unroll
    for (int i = 0; i < 4; i++) {
        float inv = 1.0f / rsum[i];
        size_t row = (size_t)(b * S_) + q0 + ty * 4 + i;
        float* dst = Og + (row * NH_ + h) * HD_ + tx * 16;
#pragma unroll
        for (int t = 0; t < 4; t++) {
            float4 w = {o[i][4 * t + 0] * inv, o[i][4 * t + 1] * inv,
                        o[i][4 * t + 2] * inv, o[i][4 * t + 3] * inv};
            *(float4*)(dst + 4 * t) = w;
        }
    }
}

// ---------------------------------------------------------------------------
// Launch
// ---------------------------------------------------------------------------
extern "C" void kernel_launch(void* const* d_in, const int* in_sizes, int n_in,
                              void* d_out, int out_size)
{
    const float* hidden    = (const float*)d_in[0];
    const int*   positions = (const int*)d_in[1];
    const float* Wq        = (const float*)d_in[2];
    const float* bq        = (const float*)d_in[3];
    const float* Wk        = (const float*)d_in[4];
    const float* bk        = (const float*)d_in[5];
    const float* Wv        = (const float*)d_in[6];
    const float* bv        = (const float*)d_in[7];
    const float* Wo        = (const float*)d_in[8];
    float* out = (float*)d_out;

    float *qp, *kp, *vp, *ap;
    cudaGetSymbolAddress((void**)&qp, g_q);
    cudaGetSymbolAddress((void**)&kp, g_k);
    cudaGetSymbolAddress((void**)&vp, g_v);
    cudaGetSymbolAddress((void**)&ap, g_attn);

    const int M = B_ * S_;  // 8192

    // QKV projections
    sgemm128<<<dim3((NH_ * HD_) / 128, M / 128), 256>>>(hidden, Wq, bq, qp, M, NH_ * HD_, H_);
    sgemm128<<<dim3((NKV_ * HD_) / 128, M / 128), 256>>>(hidden, Wk, bk, kp, M, NKV_ * HD_, H_);
    sgemm128<<<dim3((NKV_ * HD_) / 128, M / 128), 256>>>(hidden, Wv, bv, vp, M, NKV_ * HD_, H_);

    // RoPE
    {
        int total = B_ * S_ * (NH_ + NKV_) * (HD_ / 2);
        rope_kernel<<<(total + 255) / 256, 256>>>(qp, kp, positions);
    }

    // Attention
    {
        size_t smem = (size_t)(256 * QT_LD + 256 * QT_LD + 64 * 256 + 64 * QT_LD) * sizeof(float);
        cudaFuncSetAttribute(attn_kernel, cudaFuncAttributeMaxDynamicSharedMemorySize, (int)smem);
        attn_kernel<<<dim3(S_ / 64, NH_, B_), 256, smem>>>(qp, kp, vp, ap);
    }

    // Output projection
    sgemm128<<<dim3(H_ / 128, M / 128), 256>>>(ap, Wo, nullptr, out, M, H_, NH_ * HD_);
}

// round 3
// speedup vs baseline: 1.5208x; 1.5208x over previous
#include <cuda_runtime.h>
#include <cuda_bf16.h>
#include <math.h>
#include <stdint.h>

// Problem constants (Gemma2 attention layer)
#define B_ 4
#define S_ 2048
#define H_ 2048
#define NH_ 8
#define NKV_ 4
#define HD_ 256
#define WIN_ 1024
#define SCALE_ 0.0625f   // 256^-0.5

#define GK_   2048       // inner K of every GEMM
#define GK3   6144       // 3x split K
#define KC    64         // K-chunk per pipeline stage
#define NC    96         // GK3 / KC
#define NSTAGE 3
#define LDS_K 72         // padded smem k-stride (bf16 elems), 144B rows

// ---------------------------------------------------------------------------
// Scratch (device globals — no allocation allowed)
// ---------------------------------------------------------------------------
__device__ float g_q[(size_t)B_ * S_ * NH_ * HD_];            // 67 MB
__device__ float g_k[(size_t)B_ * S_ * NKV_ * HD_];           // 33.5 MB
__device__ float g_v[(size_t)B_ * S_ * NKV_ * HD_];           // 33.5 MB
__device__ float g_attn[(size_t)B_ * S_ * NH_ * HD_];         // 67 MB
__device__ __nv_bfloat16 g_a3[(size_t)B_ * S_ * GK3];         // 100.7 MB
__device__ __nv_bfloat16 g_w3[(size_t)H_ * GK3];              // 25.2 MB

// ---------------------------------------------------------------------------
// Helpers
// ---------------------------------------------------------------------------
__device__ __forceinline__ uint32_t smem_u32(const void* p) {
    uint32_t a;
    asm("{ .reg .u64 t; cvta.to.shared.u64 t, %1; cvt.u32.u64 %0, t; }" : "=r"(a) : "l"(p));
    return a;
}
__device__ __forceinline__ void cp16(uint32_t dst, const void* src) {
    asm volatile("cp.async.cg.shared.global [%0], [%1], 16;" :: "r"(dst), "l"(src));
}
#define CP_COMMIT() asm volatile("cp.async.commit_group;" ::: "memory")
#define CP_WAIT1()  asm volatile("cp.async.wait_group 1;" ::: "memory")

__device__ __forceinline__ void mma16816(float* c, const uint32_t* a, const uint32_t* b) {
    asm volatile(
        "mma.sync.aligned.m16n8k16.row.col.f32.bf16.bf16.f32 "
        "{%0,%1,%2,%3}, {%4,%5,%6,%7}, {%8,%9}, {%0,%1,%2,%3};"
        : "+f"(c[0]), "+f"(c[1]), "+f"(c[2]), "+f"(c[3])
        : "r"(a[0]), "r"(a[1]), "r"(a[2]), "r"(a[3]), "r"(b[0]), "r"(b[1]));
}

// ---------------------------------------------------------------------------
// Split-precision conversions
// ---------------------------------------------------------------------------
// A3[m, 0:2048)=hi, [2048:4096)=hi, [4096:6144)=lo
__global__ __launch_bounds__(256) void convA(const float* __restrict__ A,
                                             __nv_bfloat16* __restrict__ A3)
{
    int idx = blockIdx.x * 256 + threadIdx.x;        // M * 512 threads
    int m = idx >> 9;
    int j = (idx & 511) * 4;
    float4 v = *(const float4*)(A + (size_t)m * GK_ + j);
    float xs[4] = {v.x, v.y, v.z, v.w};
    __nv_bfloat16 h[4], l[4];
#pragma unroll
    for (int i = 0; i < 4; i++) {
        h[i] = __float2bfloat16_rn(xs[i]);
        l[i] = __float2bfloat16_rn(xs[i] - __bfloat162float(h[i]));
    }
    size_t r = (size_t)m * GK3 + j;
    *(uint2*)&A3[r]             = *(uint2*)h;
    *(uint2*)&A3[r + GK_]       = *(uint2*)h;
    *(uint2*)&A3[r + 2 * GK_]   = *(uint2*)l;
}

// W[k][n] (K=2048, width N) -> W3[n, 0:2048)=hi, [2048:4096)=lo, [4096:6144)=hi
__global__ __launch_bounds__(256) void convW(const float* __restrict__ W,
                                             __nv_bfloat16* __restrict__ W3, int N)
{
    __shared__ float t[32][33];
    int n0 = blockIdx.x * 32, k0 = blockIdx.y * 32;
    int tx = threadIdx.x & 31, ty = threadIdx.x >> 5;   // 32 x 8
#pragma unroll
    for (int i = 0; i < 32; i += 8)
        t[ty + i][tx] = W[(size_t)(k0 + ty + i) * N + n0 + tx];
    __syncthreads();
#pragma unroll
    for (int i = 0; i < 32; i += 8) {
        int n = n0 + ty + i, k = k0 + tx;
        float x = t[tx][ty + i];
        __nv_bfloat16 h = __float2bfloat16_rn(x);
        __nv_bfloat16 l = __float2bfloat16_rn(x - __bfloat162float(h));
        size_t r = (size_t)n * GK3 + k;
        W3[r] = h;
        W3[r + GK_] = l;
        W3[r + 2 * GK_] = h;
    }
}

// ---------------------------------------------------------------------------
// mma.sync bf16 GEMM: C[8192, Nn] = A3[8192, 6144] @ B3[Nn, 6144]^T + bias
// CTA: 128x128, 8 warps (2m x 4n), warp tile 64x32 (4x4 m16n8k16).
// 3-stage cp.async pipeline, K-chunk 64.
// Grid: (Nn/128, 64). Block: 256.
// ---------------------------------------------------------------------------
__global__ __launch_bounds__(256) void gemm_mma(
    const __nv_bfloat16* __restrict__ A3, const __nv_bfloat16* __restrict__ B3,
    const float* __restrict__ bias, float* __restrict__ C, int Nn)
{
    extern __shared__ __align__(16) char smraw[];
    __nv_bfloat16* sA = (__nv_bfloat16*)smraw;               // [NSTAGE][128][LDS_K]
    __nv_bfloat16* sB = sA + NSTAGE * 128 * LDS_K;           // [NSTAGE][128][LDS_K]
    float* sbias = (float*)(sB + NSTAGE * 128 * LDS_K);      // [128]

    const int tid = threadIdx.x;
    const int m0 = blockIdx.y * 128;
    const int n0 = blockIdx.x * 128;

    if (tid < 128) sbias[tid] = bias ? bias[n0 + tid] : 0.f;

    const int seg = tid & 7;      // 16B segment within 64-elem k-chunk
    const int r0  = tid >> 3;     // 0..31, + {0,32,64,96}
    const __nv_bfloat16* Ag = A3 + (size_t)m0 * GK3 + seg * 8;
    const __nv_bfloat16* Bg = B3 + (size_t)n0 * GK3 + seg * 8;
    const uint32_t sAu = smem_u32(sA);
    const uint32_t sBu = smem_u32(sB);

    // stage loader: 128 rows x 64 k of A and B
#define LOAD_STAGE(chunk, st) do {                                              \
    int _k0 = (chunk) * KC;                                                     \
    uint32_t _da = sAu + (uint32_t)(st) * 128 * LDS_K * 2;                      \
    uint32_t _db = sBu + (uint32_t)(st) * 128 * LDS_K * 2;                      \
    _Pragma("unroll")                                                           \
    for (int _rr = 0; _rr < 4; _rr++) {                                         \
        int _row = r0 + _rr * 32;                                               \
        uint32_t _o = (uint32_t)(_row * LDS_K + seg * 8) * 2;                   \
        cp16(_da + _o, Ag + (size_t)_row * GK3 + _k0);                          \
        cp16(_db + _o, Bg + (size_t)_row * GK3 + _k0);                          \
    }                                                                           \
} while (0)

    const int wid = tid >> 5, lane = tid & 31;
    const int wm = (wid >> 2) * 64;   // 0 or 64
    const int wn = (wid & 3) * 32;    // 0,32,64,96
    const int g = lane >> 2, t = lane & 3;

    float acc[4][4][4];
#pragma unroll
    for (int mi = 0; mi < 4; mi++)
#pragma unroll
        for (int ni = 0; ni < 4; ni++)
#pragma unroll
            for (int e = 0; e < 4; e++) acc[mi][ni][e] = 0.f;

    // prologue
    LOAD_STAGE(0, 0); CP_COMMIT();
    LOAD_STAGE(1, 1); CP_COMMIT();

    for (int c = 0; c < NC; c++) {
        CP_WAIT1();          // chunk c resident (this thread)
        __syncthreads();     // all threads' chunk-c data visible; prev compute done

        int lc = c + 2;
        int st_ld = lc - (lc / 3) * 3;
        if (lc < NC) LOAD_STAGE(lc, st_ld);
        CP_COMMIT();

        int st = c - (c / 3) * 3;
        const __nv_bfloat16* As = sA + st * 128 * LDS_K;
        const __nv_bfloat16* Bs = sB + st * 128 * LDS_K;

#pragma unroll
        for (int ks = 0; ks < 4; ks++) {
            const int kk = ks * 16;
            uint32_t af[4][4], bfr[4][2];
#pragma unroll
            for (int mi = 0; mi < 4; mi++) {
                const __nv_bfloat16* ap = As + (wm + mi * 16 + g) * LDS_K + kk + 2 * t;
                af[mi][0] = *(const uint32_t*)(ap);
                af[mi][1] = *(const uint32_t*)(ap + 8 * LDS_K);
                af[mi][2] = *(const uint32_t*)(ap + 8);
                af[mi][3] = *(const uint32_t*)(ap + 8 * LDS_K + 8);
            }
#pragma unroll
            for (int ni = 0; ni < 4; ni++) {
                const __nv_bfloat16* bp = Bs + (wn + ni * 8 + g) * LDS_K + kk + 2 * t;
                bfr[ni][0] = *(const uint32_t*)(bp);
                bfr[ni][1] = *(const uint32_t*)(bp + 8);
            }
#pragma unroll
            for (int mi = 0; mi < 4; mi++)
#pragma unroll
                for (int ni = 0; ni < 4; ni++)
                    mma16816(acc[mi][ni], af[mi], bfr[ni]);
        }
    }

    __syncthreads();
    // epilogue: acc -> C (+bias)
#pragma unroll
    for (int mi = 0; mi < 4; mi++) {
        int row = m0 + wm + mi * 16 + g;
#pragma unroll
        for (int ni = 0; ni < 4; ni++) {
            int lcol = wn + ni * 8 + 2 * t;
            float b0 = sbias[lcol], b1 = sbias[lcol + 1];
            float2 v0 = {acc[mi][ni][0] + b0, acc[mi][ni][1] + b1};
            float2 v1 = {acc[mi][ni][2] + b0, acc[mi][ni][3] + b1};
            *(float2*)(C + (size_t)row * Nn + n0 + lcol) = v0;
            *(float2*)(C + (size_t)(row + 8) * Nn + n0 + lcol) = v1;
        }
    }
#undef LOAD_STAGE
}

// ---------------------------------------------------------------------------
// RoPE (NeoX), in-place on q (8 heads) and k (4 heads).
// ---------------------------------------------------------------------------
__global__ void rope_kernel(float* __restrict__ q, float* __restrict__ k,
                            const int* __restrict__ positions)
{
    const int total = B_ * S_ * (NH_ + NKV_) * (HD_ / 2);
    int idx = blockIdx.x * blockDim.x + threadIdx.x;
    if (idx >= total) return;
    const int d = idx & 127;
    int r = idx >> 7;
    const int head = r % (NH_ + NKV_);
    const int bs = r / (NH_ + NKV_);
    const int pos = positions[bs];

    const float inv_freq = powf(10000.0f, -(float)d * (1.0f / 128.0f));
    const float fr = (float)pos * inv_freq;
    float sn, cs;
    sincosf(fr, &sn, &cs);

    float* base;
    if (head < NH_)
        base = q + ((size_t)bs * NH_ + head) * HD_;
    else
        base = k + ((size_t)bs * NKV_ + (head - NH_)) * HD_;

    const float x1 = base[d];
    const float x2 = base[d + 128];
    base[d]       = x1 * cs - x2 * sn;
    base[d + 128] = x2 * cs + x1 * sn;
}

// ---------------------------------------------------------------------------
// Sliding-window flash attention, fp32 SIMT.
// ---------------------------------------------------------------------------
#define QT_LD 68

__global__ __launch_bounds__(256) void attn_kernel(
    const float* __restrict__ Qg, const float* __restrict__ Kg,
    const float* __restrict__ Vg, float* __restrict__ Og)
{
    extern __shared__ float sm[];
    float* Qt  = sm;
    float* Kt  = Qt + 256 * QT_LD;
    float* Vs  = Kt + 256 * QT_LD;
    float* Pst = Vs + 64 * 256;

    const int tid = threadIdx.x;
    const int tx = tid & 15;
    const int ty = tid >> 4;
    const int q0 = blockIdx.x * 64;
    const int h = blockIdx.y;
    const int b = blockIdx.z;
    const int kvh = h >> 1;

    for (int idx = tid; idx < 64 * 64; idx += 256) {
        int n = idx >> 6;
        int d = (idx & 63) * 4;
        size_t base = ((size_t)((b * S_ + q0 + n) * NH_ + h)) * HD_ + d;
        float4 v4 = *(const float4*)(Qg + base);
        Qt[(d + 0) * QT_LD + n] = v4.x;
        Qt[(d + 1) * QT_LD + n] = v4.y;
        Qt[(d + 2) * QT_LD + n] = v4.z;
        Qt[(d + 3) * QT_LD + n] = v4.w;
    }

    float o[4][16];
#pragma unroll
    for (int i = 0; i < 4; i++)
#pragma unroll
        for (int j = 0; j < 16; j++) o[i][j] = 0.f;

    float rmax[4], rsum[4];
#pragma unroll
    for (int i = 0; i < 4; i++) { rmax[i] = -1e30f; rsum[i] = 0.f; }

    int jlo = q0 - (WIN_ - 1);
    if (jlo < 0) jlo = 0;
    const int jt0 = (jlo / 64) * 64;

    for (int jt = jt0; jt <= q0; jt += 64) {
        __syncthreads();
        for (int idx = tid; idx < 64 * 64; idx += 256) {
            int n = idx >> 6;
            int d = (idx & 63) * 4;
            size_t base = ((size_t)((b * S_ + jt + n) * NKV_ + kvh)) * HD_ + d;
            float4 k4 = *(const float4*)(Kg + base);
            float4 v4 = *(const float4*)(Vg + base);
            Kt[(d + 0) * QT_LD + n] = k4.x;
            Kt[(d + 1) * QT_LD + n] = k4.y;
            Kt[(d + 2) * QT_LD + n] = k4.z;
            Kt[(d + 3) * QT_LD + n] = k4.w;
            *(float4*)&Vs[n * 256 + d] = v4;
        }
        __syncthreads();

        float s[4][4];
#pragma unroll
        for (int i = 0; i < 4; i++)
#pragma unroll
            for (int j = 0; j < 4; j++) s[i][j] = 0.f;

        const float* qtp = Qt + ty * 4;
        const float* ktp = Kt + tx * 4;
#pragma unroll 4
        for (int k = 0; k < 256; k++) {
            float4 qa = *(const float4*)(qtp + k * QT_LD);
            float4 kb = *(const float4*)(ktp + k * QT_LD);
            float qv[4] = {qa.x, qa.y, qa.z, qa.w};
            float kv[4] = {kb.x, kb.y, kb.z, kb.w};
#pragma unroll
            for (int i = 0; i < 4; i++)
#pragma unroll
                for (int j = 0; j < 4; j++) s[i][j] += qv[i] * kv[j];
        }

#pragma unroll
        for (int i = 0; i < 4; i++) {
            int qi = q0 + ty * 4 + i;
#pragma unroll
            for (int j = 0; j < 4; j++) {
                int kj = jt + tx * 4 + j;
                bool valid = (kj <= qi) && (kj > qi - WIN_);
                s[i][j] = valid ? s[i][j] * SCALE_ : -1e30f;
            }
        }

#pragma unroll
        for (int i = 0; i < 4; i++) {
            float tm = fmaxf(fmaxf(s[i][0], s[i][1]), fmaxf(s[i][2], s[i][3]));
#pragma unroll
            for (int off = 8; off >= 1; off >>= 1)
                tm = fmaxf(tm, __shfl_xor_sync(0xffffffffu, tm, off));
            float newmax = fmaxf(rmax[i], tm);
            float alpha = expf(rmax[i] - newmax);
            float p[4], psum = 0.f;
#pragma unroll
            for (int j = 0; j < 4; j++) {
                p[j] = (s[i][j] > -5e29f) ? expf(s[i][j] - newmax) : 0.f;
                psum += p[j];
            }
#pragma unroll
            for (int off = 8; off >= 1; off >>= 1)
                psum += __shfl_xor_sync(0xffffffffu, psum, off);
            rsum[i] = rsum[i] * alpha + psum;
            rmax[i] = newmax;
#pragma unroll
            for (int jj = 0; jj < 16; jj++) o[i][jj] *= alpha;
#pragma unroll
            for (int j = 0; j < 4; j++)
                Pst[(tx * 4 + j) * QT_LD + ty * 4 + i] = p[j];
        }
        __syncthreads();

#pragma unroll 2
        for (int n = 0; n < 64; n++) {
            float4 p4 = *(const float4*)&Pst[n * QT_LD + ty * 4];
            float pr[4] = {p4.x, p4.y, p4.z, p4.w};
            const float* vr = Vs + n * 256 + tx * 16;
            float4 v0 = *(const float4*)(vr);
            float4 v1 = *(const float4*)(vr + 4);
            float4 v2 = *(const float4*)(vr + 8);
            float4 v3 = *(const float4*)(vr + 12);
            float vv[16] = {v0.x, v0.y, v0.z, v0.w, v1.x, v1.y, v1.z, v1.w,
                            v2.x, v2.y, v2.z, v2.w, v3.x, v3.y, v3.z, v3.w};
#pragma unroll
            for (int i = 0; i < 4; i++)
#pragma unroll
                for (int jj = 0; jj < 16; jj++) o[i][jj] += pr[i] * vv[jj];
        }
    }

#pragma unroll
    for (int i = 0; i < 4; i++) {
        float inv = 1.0f / rsum[i];
        size_t row = (size_t)(b * S_) + q0 + ty * 4 + i;
        float* dst = Og + (row * NH_ + h) * HD_ + tx * 16;
#pragma unroll
        for (int t = 0; t < 4; t++) {
            float4 w = {o[i][4 * t + 0] * inv, o[i][4 * t + 1] * inv,
                        o[i][4 * t + 2] * inv, o[i][4 * t + 3] * inv};
            *(float4*)(dst + 4 * t) = w;
        }
    }
}

// ---------------------------------------------------------------------------
// Launch
// ---------------------------------------------------------------------------
extern "C" void kernel_launch(void* const* d_in, const int* in_sizes, int n_in,
                              void* d_out, int out_size)
{
    const float* hidden    = (const float*)d_in[0];
    const int*   positions = (const int*)d_in[1];
    const float* Wq        = (const float*)d_in[2];
    const float* bq        = (const float*)d_in[3];
    const float* Wk        = (const float*)d_in[4];
    const float* bk        = (const float*)d_in[5];
    const float* Wv        = (const float*)d_in[6];
    const float* bv        = (const float*)d_in[7];
    const float* Wo        = (const float*)d_in[8];
    float* out = (float*)d_out;

    float *qp, *kp, *vp, *ap;
    __nv_bfloat16 *a3, *w3;
    cudaGetSymbolAddress((void**)&qp, g_q);
    cudaGetSymbolAddress((void**)&kp, g_k);
    cudaGetSymbolAddress((void**)&vp, g_v);
    cudaGetSymbolAddress((void**)&ap, g_attn);
    cudaGetSymbolAddress((void**)&a3, g_a3);
    cudaGetSymbolAddress((void**)&w3, g_w3);

    const int M = B_ * S_;              // 8192
    const size_t gemm_smem = (size_t)NSTAGE * 128 * LDS_K * 2 * 2 + 512;  // 111104
    cudaFuncSetAttribute(gemm_mma, cudaFuncAttributeMaxDynamicSharedMemorySize, (int)gemm_smem);

    // hidden -> split bf16
    convA<<<M * 512 / 256, 256>>>(hidden, a3);

    // Q projection
    convW<<<dim3(2048 / 32, 64), 256>>>(Wq, w3, 2048);
    gemm_mma<<<dim3(16, 64), 256, gemm_smem>>>(a3, w3, bq, qp, 2048);
    // K projection
    convW<<<dim3(1024 / 32, 64), 256>>>(Wk, w3, 1024);
    gemm_mma<<<dim3(8, 64), 256, gemm_smem>>>(a3, w3, bk, kp, 1024);
    // V projection
    convW<<<dim3(1024 / 32, 64), 256>>>(Wv, w3, 1024);
    gemm_mma<<<dim3(8, 64), 256, gemm_smem>>>(a3, w3, bv, vp, 1024);

    // RoPE
    {
        int total = B_ * S_ * (NH_ + NKV_) * (HD_ / 2);
        rope_kernel<<<(total + 255) / 256, 256>>>(qp, kp, positions);
    }

    // Attention
    {
        size_t smem = (size_t)(256 * QT_LD + 256 * QT_LD + 64 * 256 + 64 * QT_LD) * sizeof(float);
        cudaFuncSetAttribute(attn_kernel, cudaFuncAttributeMaxDynamicSharedMemorySize, (int)smem);
        attn_kernel<<<dim3(S_ / 64, NH_, B_), 256, smem>>>(qp, kp, vp, ap);
    }

    // Output projection
    convA<<<M * 512 / 256, 256>>>(ap, a3);
    convW<<<dim3(2048 / 32, 64), 256>>>(Wo, w3, 2048);
    gemm_mma<<<dim3(16, 64), 256, gemm_smem>>>(a3, w3, nullptr, out, 2048);
}

// round 4
// speedup vs baseline: 3.0955x; 2.0354x over previous
#include <cuda_runtime.h>
#include <cuda_bf16.h>
#include <math.h>
#include <stdint.h>

// Problem constants (Gemma2 attention layer)
#define B_ 4
#define S_ 2048
#define H_ 2048
#define NH_ 8
#define NKV_ 4
#define HD_ 256
#define WIN_ 1024
#define SCALE_ 0.0625f   // 256^-0.5

#define GK_   2048       // inner K of every GEMM
#define GK3   6144       // 3x split K
#define KC    64         // K-chunk per pipeline stage
#define NC    96         // GK3 / KC
#define NSTAGE 3
#define LDS_K 72         // padded smem k-stride (bf16 elems), 144B rows

// ---------------------------------------------------------------------------
// Scratch (device globals — no allocation allowed)
// ---------------------------------------------------------------------------
__device__ float g_q[(size_t)B_ * S_ * NH_ * HD_];
__device__ float g_k[(size_t)B_ * S_ * NKV_ * HD_];
__device__ float g_v[(size_t)B_ * S_ * NKV_ * HD_];
__device__ float g_attn[(size_t)B_ * S_ * NH_ * HD_];
__device__ __nv_bfloat16 g_a3[(size_t)B_ * S_ * GK3];
__device__ __nv_bfloat16 g_w3[(size_t)H_ * GK3];
// attention operands (hi|lo split)
__device__ __nv_bfloat16 g_q2[(size_t)B_ * NH_ * S_ * 512];   // [b][h][s][qhi(256)|qlo(256)]
__device__ __nv_bfloat16 g_k2[(size_t)B_ * NKV_ * S_ * 512];  // [b][kvh][s][khi|klo]
__device__ __nv_bfloat16 g_vt[(size_t)B_ * NKV_ * 512 * S_];  // [b][kvh][vhi d(256)|vlo d(256)][s]

// ---------------------------------------------------------------------------
// Helpers
// ---------------------------------------------------------------------------
__device__ __forceinline__ uint32_t smem_u32(const void* p) {
    uint32_t a;
    asm("{ .reg .u64 t; cvta.to.shared.u64 t, %1; cvt.u32.u64 %0, t; }" : "=r"(a) : "l"(p));
    return a;
}
__device__ __forceinline__ void cp16(uint32_t dst, const void* src) {
    asm volatile("cp.async.cg.shared.global [%0], [%1], 16;" :: "r"(dst), "l"(src));
}
#define CP_COMMIT() asm volatile("cp.async.commit_group;" ::: "memory")
#define CP_WAIT1()  asm volatile("cp.async.wait_group 1;" ::: "memory")

__device__ __forceinline__ void mma16816(float* c, const uint32_t* a, const uint32_t* b) {
    asm volatile(
        "mma.sync.aligned.m16n8k16.row.col.f32.bf16.bf16.f32 "
        "{%0,%1,%2,%3}, {%4,%5,%6,%7}, {%8,%9}, {%0,%1,%2,%3};"
        : "+f"(c[0]), "+f"(c[1]), "+f"(c[2]), "+f"(c[3])
        : "r"(a[0]), "r"(a[1]), "r"(a[2]), "r"(a[3]), "r"(b[0]), "r"(b[1]));
}
#define LDSM4(r, a)                                                             \
    asm volatile("ldmatrix.sync.aligned.m8n8.x4.shared.b16 {%0,%1,%2,%3}, [%4];" \
        : "=r"((r)[0]), "=r"((r)[1]), "=r"((r)[2]), "=r"((r)[3]) : "r"(a))

__device__ __forceinline__ uint32_t packbf(float x, float y) {
    __nv_bfloat162 t = __floats2bfloat162_rn(x, y);
    return *(uint32_t*)&t;
}

// ---------------------------------------------------------------------------
// Split-precision conversions for GEMM
// ---------------------------------------------------------------------------
__global__ __launch_bounds__(256) void convA(const float* __restrict__ A,
                                             __nv_bfloat16* __restrict__ A3)
{
    int idx = blockIdx.x * 256 + threadIdx.x;
    int m = idx >> 9;
    int j = (idx & 511) * 4;
    float4 v = *(const float4*)(A + (size_t)m * GK_ + j);
    float xs[4] = {v.x, v.y, v.z, v.w};
    __nv_bfloat16 h[4], l[4];
#pragma unroll
    for (int i = 0; i < 4; i++) {
        h[i] = __float2bfloat16_rn(xs[i]);
        l[i] = __float2bfloat16_rn(xs[i] - __bfloat162float(h[i]));
    }
    size_t r = (size_t)m * GK3 + j;
    *(uint2*)&A3[r]           = *(uint2*)h;
    *(uint2*)&A3[r + GK_]     = *(uint2*)h;
    *(uint2*)&A3[r + 2 * GK_] = *(uint2*)l;
}

__global__ __launch_bounds__(256) void convW(const float* __restrict__ W,
                                             __nv_bfloat16* __restrict__ W3, int N)
{
    __shared__ float t[32][33];
    int n0 = blockIdx.x * 32, k0 = blockIdx.y * 32;
    int tx = threadIdx.x & 31, ty = threadIdx.x >> 5;
#pragma unroll
    for (int i = 0; i < 32; i += 8)
        t[ty + i][tx] = W[(size_t)(k0 + ty + i) * N + n0 + tx];
    __syncthreads();
#pragma unroll
    for (int i = 0; i < 32; i += 8) {
        int n = n0 + ty + i, k = k0 + tx;
        float x = t[tx][ty + i];
        __nv_bfloat16 h = __float2bfloat16_rn(x);
        __nv_bfloat16 l = __float2bfloat16_rn(x - __bfloat162float(h));
        size_t r = (size_t)n * GK3 + k;
        W3[r] = h;
        W3[r + GK_] = l;
        W3[r + 2 * GK_] = h;
    }
}

// ---------------------------------------------------------------------------
// mma.sync bf16 GEMM (ldmatrix fragment loads)
// ---------------------------------------------------------------------------
__global__ __launch_bounds__(256) void gemm_mma(
    const __nv_bfloat16* __restrict__ A3, const __nv_bfloat16* __restrict__ B3,
    const float* __restrict__ bias, float* __restrict__ C, int Nn)
{
    extern __shared__ __align__(16) char smraw[];
    __nv_bfloat16* sA = (__nv_bfloat16*)smraw;
    __nv_bfloat16* sB = sA + NSTAGE * 128 * LDS_K;
    float* sbias = (float*)(sB + NSTAGE * 128 * LDS_K);

    const int tid = threadIdx.x;
    const int m0 = blockIdx.y * 128;
    const int n0 = blockIdx.x * 128;

    if (tid < 128) sbias[tid] = bias ? bias[n0 + tid] : 0.f;

    const int seg = tid & 7;
    const int r0  = tid >> 3;
    const __nv_bfloat16* Ag = A3 + (size_t)m0 * GK3 + seg * 8;
    const __nv_bfloat16* Bg = B3 + (size_t)n0 * GK3 + seg * 8;
    const uint32_t sAu = smem_u32(sA);
    const uint32_t sBu = smem_u32(sB);

#define LOAD_STAGE(chunk, st) do {                                              \
    int _k0 = (chunk) * KC;                                                     \
    uint32_t _da = sAu + (uint32_t)(st) * 18432;                                \
    uint32_t _db = sBu + (uint32_t)(st) * 18432;                                \
    _Pragma("unroll")                                                           \
    for (int _rr = 0; _rr < 4; _rr++) {                                         \
        int _row = r0 + _rr * 32;                                               \
        uint32_t _o = (uint32_t)(_row * LDS_K + seg * 8) * 2;                   \
        cp16(_da + _o, Ag + (size_t)_row * GK3 + _k0);                          \
        cp16(_db + _o, Bg + (size_t)_row * GK3 + _k0);                          \
    }                                                                           \
} while (0)

    const int wid = tid >> 5, lane = tid & 31;
    const int wm = (wid >> 2) * 64;
    const int wn = (wid & 3) * 32;
    const int g = lane >> 2, t = lane & 3;

    // ldmatrix per-thread offsets (bytes)
    const uint32_t aOff = (uint32_t)((wm + (lane & 15)) * 144 + (lane >> 4) * 16);
    const uint32_t bOff = (uint32_t)((wn + ((lane >> 4) << 3) + (lane & 7)) * 144 +
                                     ((lane >> 3) & 1) * 16);

    float acc[4][4][4];
#pragma unroll
    for (int mi = 0; mi < 4; mi++)
#pragma unroll
        for (int ni = 0; ni < 4; ni++)
#pragma unroll
            for (int e = 0; e < 4; e++) acc[mi][ni][e] = 0.f;

    LOAD_STAGE(0, 0); CP_COMMIT();
    LOAD_STAGE(1, 1); CP_COMMIT();

    for (int c = 0; c < NC; c++) {
        CP_WAIT1();
        __syncthreads();

        int lc = c + 2;
        int st_ld = lc - (lc / 3) * 3;
        if (lc < NC) LOAD_STAGE(lc, st_ld);
        CP_COMMIT();

        int st = c - (c / 3) * 3;
        const uint32_t aS = sAu + st * 18432 + aOff;
        const uint32_t bS = sBu + st * 18432 + bOff;

#pragma unroll
        for (int ks = 0; ks < 4; ks++) {
            uint32_t af[4][4], bq[2][4];
#pragma unroll
            for (int mi = 0; mi < 4; mi++) LDSM4(af[mi], aS + mi * 2304 + ks * 32);
#pragma unroll
            for (int p = 0; p < 2; p++) LDSM4(bq[p], bS + p * 2304 + ks * 32);
#pragma unroll
            for (int mi = 0; mi < 4; mi++)
#pragma unroll
                for (int ni = 0; ni < 4; ni++)
                    mma16816(acc[mi][ni], af[mi], &bq[ni >> 1][(ni & 1) * 2]);
        }
    }

    __syncthreads();
#pragma unroll
    for (int mi = 0; mi < 4; mi++) {
        int row = m0 + wm + mi * 16 + g;
#pragma unroll
        for (int ni = 0; ni < 4; ni++) {
            int lcol = wn + ni * 8 + 2 * t;
            float b0 = sbias[lcol], b1 = sbias[lcol + 1];
            float2 v0 = {acc[mi][ni][0] + b0, acc[mi][ni][1] + b1};
            float2 v1 = {acc[mi][ni][2] + b0, acc[mi][ni][3] + b1};
            *(float2*)(C + (size_t)row * Nn + n0 + lcol) = v0;
            *(float2*)(C + (size_t)(row + 8) * Nn + n0 + lcol) = v1;
        }
    }
#undef LOAD_STAGE
}

// ---------------------------------------------------------------------------
// Fused RoPE + scale + hi/lo bf16 split for Q and K.
// thread: (b*s, head 0..11, dgroup 0..31 handling 4 rotation pairs)
// ---------------------------------------------------------------------------
__global__ __launch_bounds__(256) void conv_qk(
    const float* __restrict__ q, const float* __restrict__ k,
    const int* __restrict__ positions,
    __nv_bfloat16* __restrict__ Q2, __nv_bfloat16* __restrict__ K2)
{
    int idx = blockIdx.x * 256 + threadIdx.x;   // 4*2048*12*32
    int dg = idx & 31;
    int r = idx >> 5;
    int head = r % 12;
    int bs = r / 12;
    int b = bs >> 11, s = bs & 2047;
    int pos = positions[bs];
    int d0 = dg * 4;

    const float* src;
    __nv_bfloat16* dst;
    float sc;
    if (head < NH_) {
        src = q + ((size_t)bs * NH_ + head) * HD_;
        dst = Q2 + ((size_t)(b * NH_ + head) * S_ + s) * 512;
        sc = SCALE_;
    } else {
        int kvh = head - NH_;
        src = k + ((size_t)bs * NKV_ + kvh) * HD_;
        dst = K2 + ((size_t)(b * NKV_ + kvh) * S_ + s) * 512;
        sc = 1.0f;
    }
    float4 x1 = *(const float4*)(src + d0);
    float4 x2 = *(const float4*)(src + d0 + 128);
    float a1[4] = {x1.x, x1.y, x1.z, x1.w};
    float a2[4] = {x2.x, x2.y, x2.z, x2.w};
    __nv_bfloat16 h1[4], l1[4], h2[4], l2[4];
#pragma unroll
    for (int e = 0; e < 4; e++) {
        int d = d0 + e;
        float inv_freq = powf(10000.0f, -(float)d * (1.0f / 128.0f));
        float fr = (float)pos * inv_freq;
        float sn, cs;
        sincosf(fr, &sn, &cs);
        float y1 = (a1[e] * cs - a2[e] * sn) * sc;
        float y2 = (a2[e] * cs + a1[e] * sn) * sc;
        h1[e] = __float2bfloat16_rn(y1);
        l1[e] = __float2bfloat16_rn(y1 - __bfloat162float(h1[e]));
        h2[e] = __float2bfloat16_rn(y2);
        l2[e] = __float2bfloat16_rn(y2 - __bfloat162float(h2[e]));
    }
    *(uint2*)(dst + d0)       = *(uint2*)h1;
    *(uint2*)(dst + 128 + d0) = *(uint2*)h2;
    *(uint2*)(dst + 256 + d0) = *(uint2*)l1;
    *(uint2*)(dst + 384 + d0) = *(uint2*)l2;
}

// ---------------------------------------------------------------------------
// V transpose + hi/lo split: g_v [b][s][kvh][256] -> g_vt [b][kvh][512][S]
// ---------------------------------------------------------------------------
__global__ __launch_bounds__(256) void conv_v(const float* __restrict__ v,
                                              __nv_bfloat16* __restrict__ Vt)
{
    __shared__ float tile[32][33];
    int s0 = blockIdx.x * 32, d0 = blockIdx.y * 32;
    int b = blockIdx.z >> 2, kvh = blockIdx.z & 3;
    int tx = threadIdx.x & 31, ty = threadIdx.x >> 5;
#pragma unroll
    for (int i = 0; i < 32; i += 8)
        tile[ty + i][tx] = v[((size_t)(b * S_ + s0 + ty + i) * NKV_ + kvh) * HD_ + d0 + tx];
    __syncthreads();
    size_t base = (size_t)(b * NKV_ + kvh) * 512;
#pragma unroll
    for (int i = 0; i < 32; i += 8) {
        float x = tile[tx][ty + i];
        __nv_bfloat16 h = __float2bfloat16_rn(x);
        __nv_bfloat16 l = __float2bfloat16_rn(x - __bfloat162float(h));
        int d = d0 + ty + i;
        Vt[(base + d) * S_ + s0 + tx]       = h;
        Vt[(base + 256 + d) * S_ + s0 + tx] = l;
    }
}

// ---------------------------------------------------------------------------
// Tensor-core sliding-window flash attention.
// grid (S/128, NH, B), block 256 (8 warps, each owns 16 q-rows, all 256 d).
// kv-tile 32. QK: 3-pass split (qh*kh + qh*kl + ql*kh). PV: ph*vh+pl*vh+ph*vl.
// ---------------------------------------------------------------------------
#define QLD 520      // bf16 elems per Q smem row (512 + 8 pad)
#define VLD 40       // bf16 elems per V smem row (32 + 8 pad)

__global__ __launch_bounds__(256, 1) void attn_mma(
    const __nv_bfloat16* __restrict__ Q2, const __nv_bfloat16* __restrict__ K2,
    const __nv_bfloat16* __restrict__ Vt, float* __restrict__ Og)
{
    extern __shared__ __align__(16) __nv_bfloat16 smb[];
    __nv_bfloat16* Qs = smb;                 // [128][520]
    __nv_bfloat16* Ks = Qs + 128 * QLD;      // [32][520]
    __nv_bfloat16* Vs = Ks + 32 * QLD;       // [512][40]

    const int tid = threadIdx.x;
    const int w = tid >> 5, lane = tid & 31;
    const int g = lane >> 2, t = lane & 3;
    const int q0 = blockIdx.x * 128;
    const int h = blockIdx.y;
    const int b = blockIdx.z;
    const int kvh = h >> 1;

    const uint32_t QsA = smem_u32(Qs);
    const uint32_t KsA = smem_u32(Ks);
    const uint32_t VsA = smem_u32(Vs);

    const __nv_bfloat16* Qg = Q2 + ((size_t)(b * NH_ + h) * S_ + q0) * 512;
    const __nv_bfloat16* Kg = K2 + (size_t)(b * NKV_ + kvh) * S_ * 512;
    const __nv_bfloat16* Vg = Vt + (size_t)(b * NKV_ + kvh) * 512 * S_;

    // ldmatrix per-thread base addrs
    const uint32_t qA = QsA + (uint32_t)((w * 16 + (lane & 15)) * QLD * 2 + (lane >> 4) * 16);
    const uint32_t kB = KsA + (uint32_t)((((lane >> 4) << 3) + (lane & 7)) * QLD * 2 +
                                         ((lane >> 3) & 1) * 16);
    const uint32_t vB = VsA + (uint32_t)((((lane >> 4) << 3) + (lane & 7)) * VLD * 2 +
                                         ((lane >> 3) & 1) * 16);

    // ---- load Q tile (group 0)
#pragma unroll
    for (int it = 0; it < 32; it++) {
        int idx = tid + it * 256;
        int r = idx >> 6, seg = idx & 63;
        cp16(QsA + (uint32_t)(r * QLD + seg * 8) * 2, Qg + (size_t)r * 512 + seg * 8);
    }
    CP_COMMIT();

    // kv range
    int lo = q0 - (WIN_ - 1); if (lo < 0) lo = 0;
    const int kt0 = (lo >> 5) << 5;
    const int ntiles = ((q0 + 96) - kt0) / 32 + 1;

#define LOAD_K(kt) do {                                                         \
    _Pragma("unroll")                                                           \
    for (int _it = 0; _it < 8; _it++) {                                         \
        int _i = tid + _it * 256;                                               \
        int _r = _i >> 6, _sg = _i & 63;                                        \
        cp16(KsA + (uint32_t)(_r * QLD + _sg * 8) * 2,                          \
             Kg + ((size_t)((kt) + _r)) * 512 + _sg * 8);                       \
    }                                                                           \
} while (0)
#define LOAD_V(kt) do {                                                         \
    _Pragma("unroll")                                                           \
    for (int _it = 0; _it < 8; _it++) {                                         \
        int _i = tid + _it * 256;                                               \
        int _r = _i >> 2, _sg = _i & 3;                                         \
        cp16(VsA + (uint32_t)(_r * VLD + _sg * 8) * 2,                          \
             Vg + (size_t)_r * S_ + (kt) + _sg * 8);                            \
    }                                                                           \
} while (0)

    LOAD_K(kt0); CP_COMMIT();
    LOAD_V(kt0); CP_COMMIT();

    float o[32][4];
#pragma unroll
    for (int nt = 0; nt < 32; nt++)
#pragma unroll
        for (int e = 0; e < 4; e++) o[nt][e] = 0.f;
    float rmax0 = -1e20f, rmax1 = -1e20f, rsum0 = 0.f, rsum1 = 0.f;

    const int rmin = q0 + w * 16;       // warp's lowest q row
    const int rmax_w = rmin + 15;
    const int row0 = rmin + g;
    const int row1 = row0 + 8;
    const int tcol = 2 * t;

    for (int j = 0; j < ntiles; j++) {
        const int kt = kt0 + 32 * j;
        const bool skipT = (kt > rmax_w) || (kt + 31 < rmin - (WIN_ - 1));
        const bool edge = !((kt + 31 <= rmin) && (kt >= rmax_w - (WIN_ - 1)));

        CP_WAIT1();            // K_j (and Q on j=0) resident
        __syncthreads();

        float s[4][4];
        if (!skipT) {
#pragma unroll
            for (int nt = 0; nt < 4; nt++)
#pragma unroll
                for (int e = 0; e < 4; e++) s[nt][e] = 0.f;
            const int qoffs[3] = {0, 0, 512};      // bytes = elems*2 applied below
            const int koffs[3] = {0, 512, 0};
#pragma unroll
            for (int pass = 0; pass < 3; pass++) {
                uint32_t qb = qA + (uint32_t)qoffs[pass];
                uint32_t kb = kB + (uint32_t)koffs[pass];
#pragma unroll 4
                for (int ks = 0; ks < 16; ks++) {
                    uint32_t a[4], b0[4], b1[4];
                    LDSM4(a, qb + ks * 32);
                    LDSM4(b0, kb + ks * 32);
                    LDSM4(b1, kb + 16 * QLD * 2 + ks * 32);
                    mma16816(s[0], a, &b0[0]);
                    mma16816(s[1], a, &b0[2]);
                    mma16816(s[2], a, &b1[0]);
                    mma16816(s[3], a, &b1[2]);
                }
            }
        }
        __syncthreads();       // all warps done with Ks
        if (j + 1 < ntiles) LOAD_K(kt + 32);
        CP_COMMIT();
        CP_WAIT1();            // V_j resident
        __syncthreads();

        uint32_t ph[4][2], pl[4][2];
        if (!skipT) {
            // mask
            if (edge) {
#pragma unroll
                for (int nt = 0; nt < 4; nt++) {
                    int c0 = kt + nt * 8 + tcol, c1 = c0 + 1;
                    if (!(c0 <= row0 && c0 > row0 - WIN_)) s[nt][0] = -1e30f;
                    if (!(c1 <= row0 && c1 > row0 - WIN_)) s[nt][1] = -1e30f;
                    if (!(c0 <= row1 && c0 > row1 - WIN_)) s[nt][2] = -1e30f;
                    if (!(c1 <= row1 && c1 > row1 - WIN_)) s[nt][3] = -1e30f;
                }
            }
            // row maxes
            float m0 = fmaxf(fmaxf(s[0][0], s[0][1]), fmaxf(s[1][0], s[1][1]));
            m0 = fmaxf(m0, fmaxf(fmaxf(s[2][0], s[2][1]), fmaxf(s[3][0], s[3][1])));
            float m1 = fmaxf(fmaxf(s[0][2], s[0][3]), fmaxf(s[1][2], s[1][3]));
            m1 = fmaxf(m1, fmaxf(fmaxf(s[2][2], s[2][3]), fmaxf(s[3][2], s[3][3])));
            m0 = fmaxf(m0, __shfl_xor_sync(0xffffffffu, m0, 1));
            m0 = fmaxf(m0, __shfl_xor_sync(0xffffffffu, m0, 2));
            m1 = fmaxf(m1, __shfl_xor_sync(0xffffffffu, m1, 1));
            m1 = fmaxf(m1, __shfl_xor_sync(0xffffffffu, m1, 2));
            float nm0 = fmaxf(rmax0, m0), nm1 = fmaxf(rmax1, m1);
            float al0 = __expf(rmax0 - nm0), al1 = __expf(rmax1 - nm1);
            float ls0 = 0.f, ls1 = 0.f;
#pragma unroll
            for (int nt = 0; nt < 4; nt++) {
                s[nt][0] = __expf(s[nt][0] - nm0);
                s[nt][1] = __expf(s[nt][1] - nm0);
                s[nt][2] = __expf(s[nt][2] - nm1);
                s[nt][3] = __expf(s[nt][3] - nm1);
                ls0 += s[nt][0] + s[nt][1];
                ls1 += s[nt][2] + s[nt][3];
            }
            ls0 += __shfl_xor_sync(0xffffffffu, ls0, 1);
            ls0 += __shfl_xor_sync(0xffffffffu, ls0, 2);
            ls1 += __shfl_xor_sync(0xffffffffu, ls1, 1);
            ls1 += __shfl_xor_sync(0xffffffffu, ls1, 2);
            rsum0 = rsum0 * al0 + ls0;
            rsum1 = rsum1 * al1 + ls1;
            rmax0 = nm0; rmax1 = nm1;
#pragma unroll
            for (int nt = 0; nt < 32; nt++) {
                o[nt][0] *= al0; o[nt][1] *= al0;
                o[nt][2] *= al1; o[nt][3] *= al1;
            }
            // pack P hi/lo
#pragma unroll
            for (int nt = 0; nt < 4; nt++) {
                __nv_bfloat162 h01 = __floats2bfloat162_rn(s[nt][0], s[nt][1]);
                __nv_bfloat162 h23 = __floats2bfloat162_rn(s[nt][2], s[nt][3]);
                ph[nt][0] = *(uint32_t*)&h01;
                ph[nt][1] = *(uint32_t*)&h23;
                pl[nt][0] = packbf(s[nt][0] - __low2float(h01), s[nt][1] - __high2float(h01));
                pl[nt][1] = packbf(s[nt][2] - __low2float(h23), s[nt][3] - __high2float(h23));
            }
            // PV
#pragma unroll
            for (int kk = 0; kk < 2; kk++) {
                uint32_t Ah[4] = {ph[2 * kk][0], ph[2 * kk][1], ph[2 * kk + 1][0], ph[2 * kk + 1][1]};
                uint32_t Al[4] = {pl[2 * kk][0], pl[2 * kk][1], pl[2 * kk + 1][0], pl[2 * kk + 1][1]};
#pragma unroll
                for (int p = 0; p < 16; p++) {
                    uint32_t rh[4], rl[4];
                    LDSM4(rh, vB + p * (16 * VLD * 2) + kk * 32);
                    mma16816(o[2 * p], Ah, &rh[0]);
                    mma16816(o[2 * p], Al, &rh[0]);
                    mma16816(o[2 * p + 1], Ah, &rh[2]);
                    mma16816(o[2 * p + 1], Al, &rh[2]);
                    LDSM4(rl, vB + 256 * VLD * 2 + p * (16 * VLD * 2) + kk * 32);
                    mma16816(o[2 * p], Ah, &rl[0]);
                    mma16816(o[2 * p + 1], Ah, &rl[2]);
                }
            }
        }
        __syncthreads();       // all warps done with Vs
        if (j + 1 < ntiles) LOAD_V(kt + 32);
        CP_COMMIT();
    }

    // epilogue
    float inv0 = 1.0f / rsum0, inv1 = 1.0f / rsum1;
    float* d0p = Og + ((size_t)(b * S_ + row0) * NH_ + h) * HD_;
    float* d1p = Og + ((size_t)(b * S_ + row1) * NH_ + h) * HD_;
#pragma unroll
    for (int nt = 0; nt < 32; nt++) {
        int d = nt * 8 + tcol;
        float2 v0 = {o[nt][0] * inv0, o[nt][1] * inv0};
        float2 v1 = {o[nt][2] * inv1, o[nt][3] * inv1};
        *(float2*)(d0p + d) = v0;
        *(float2*)(d1p + d) = v1;
    }
#undef LOAD_K
#undef LOAD_V
}

// ---------------------------------------------------------------------------
// Launch
// ---------------------------------------------------------------------------
extern "C" void kernel_launch(void* const* d_in, const int* in_sizes, int n_in,
                              void* d_out, int out_size)
{
    const float* hidden    = (const float*)d_in[0];
    const int*   positions = (const int*)d_in[1];
    const float* Wq        = (const float*)d_in[2];
    const float* bq        = (const float*)d_in[3];
    const float* Wk        = (const float*)d_in[4];
    const float* bk        = (const float*)d_in[5];
    const float* Wv        = (const float*)d_in[6];
    const float* bv        = (const float*)d_in[7];
    const float* Wo        = (const float*)d_in[8];
    float* out = (float*)d_out;

    float *qp, *kp, *vp, *ap;
    __nv_bfloat16 *a3, *w3, *q2, *k2, *vt;
    cudaGetSymbolAddress((void**)&qp, g_q);
    cudaGetSymbolAddress((void**)&kp, g_k);
    cudaGetSymbolAddress((void**)&vp, g_v);
    cudaGetSymbolAddress((void**)&ap, g_attn);
    cudaGetSymbolAddress((void**)&a3, g_a3);
    cudaGetSymbolAddress((void**)&w3, g_w3);
    cudaGetSymbolAddress((void**)&q2, g_q2);
    cudaGetSymbolAddress((void**)&k2, g_k2);
    cudaGetSymbolAddress((void**)&vt, g_vt);

    const int M = B_ * S_;
    const size_t gemm_smem = (size_t)NSTAGE * 128 * LDS_K * 2 * 2 + 512;
    cudaFuncSetAttribute(gemm_mma, cudaFuncAttributeMaxDynamicSharedMemorySize, (int)gemm_smem);

    convA<<<M * 512 / 256, 256>>>(hidden, a3);

    convW<<<dim3(2048 / 32, 64), 256>>>(Wq, w3, 2048);
    gemm_mma<<<dim3(16, 64), 256, gemm_smem>>>(a3, w3, bq, qp, 2048);
    convW<<<dim3(1024 / 32, 64), 256>>>(Wk, w3, 1024);
    gemm_mma<<<dim3(8, 64), 256, gemm_smem>>>(a3, w3, bk, kp, 1024);
    convW<<<dim3(1024 / 32, 64), 256>>>(Wv, w3, 1024);
    gemm_mma<<<dim3(8, 64), 256, gemm_smem>>>(a3, w3, bv, vp, 1024);

    // fused rope + scale + split; V transpose + split
    conv_qk<<<(B_ * S_ * 12 * 32) / 256, 256>>>(qp, kp, positions, q2, k2);
    conv_v<<<dim3(S_ / 32, HD_ / 32, B_ * NKV_), 256>>>(vp, vt);

    // tensor attention
    {
        size_t smem = (size_t)(128 * QLD + 32 * QLD + 512 * VLD) * 2;  // 207360 B
        cudaFuncSetAttribute(attn_mma, cudaFuncAttributeMaxDynamicSharedMemorySize, (int)smem);
        attn_mma<<<dim3(S_ / 128, NH_, B_), 256, smem>>>(q2, k2, vt, ap);
    }

    // output projection
    convA<<<M * 512 / 256, 256>>>(ap, a3);
    convW<<<dim3(2048 / 32, 64), 256>>>(Wo, w3, 2048);
    gemm_mma<<<dim3(16, 64), 256, gemm_smem>>>(a3, w3, nullptr, out, 2048);
}

// round 5
// speedup vs baseline: 4.5524x; 1.4706x over previous
#include <cuda_runtime.h>
#include <cuda_fp16.h>
#include <math.h>
#include <stdint.h>

// Problem constants (Gemma2 attention layer)
#define B_ 4
#define S_ 2048
#define H_ 2048
#define NH_ 8
#define NKV_ 4
#define HD_ 256
#define WIN_ 1024
#define SCALE_ 0.0625f   // 256^-0.5

#define GK_   2048       // inner K of every GEMM
#define GK2   4096       // 2x split K (A = hi|lo)
#define KC    64         // K-chunk per pipeline stage
#define NC    64         // GK2 / KC
#define NSTAGE 3
#define LDS_K 72         // padded smem k-stride (fp16 elems), 144B rows

// ---------------------------------------------------------------------------
// Scratch (device globals — no allocation allowed)
// ---------------------------------------------------------------------------
__device__ float g_q[(size_t)B_ * S_ * NH_ * HD_];
__device__ float g_k[(size_t)B_ * S_ * NKV_ * HD_];
__device__ float g_v[(size_t)B_ * S_ * NKV_ * HD_];
__device__ float g_attn[(size_t)B_ * S_ * NH_ * HD_];
__device__ __half g_a2[(size_t)B_ * S_ * GK2];                // 64 MB (hi|lo)
__device__ __half g_w2[(size_t)H_ * GK_];                     // 8 MB (single fp16)
// attention operands
__device__ __half g_q2[(size_t)B_ * NH_ * S_ * 512];          // [b][h][s][qhi(256)|qlo(256)]
__device__ __half g_k2[(size_t)B_ * NKV_ * S_ * 256];         // [b][kvh][s][khi(256)]
__device__ __half g_vt[(size_t)B_ * NKV_ * 256 * S_];         // [b][kvh][d(256)][s]

// ---------------------------------------------------------------------------
// Helpers
// ---------------------------------------------------------------------------
__device__ __forceinline__ uint32_t smem_u32(const void* p) {
    uint32_t a;
    asm("{ .reg .u64 t; cvta.to.shared.u64 t, %1; cvt.u32.u64 %0, t; }" : "=r"(a) : "l"(p));
    return a;
}
__device__ __forceinline__ void cp16(uint32_t dst, const void* src) {
    asm volatile("cp.async.cg.shared.global [%0], [%1], 16;" :: "r"(dst), "l"(src));
}
#define CP_COMMIT() asm volatile("cp.async.commit_group;" ::: "memory")
#define CP_WAIT1()  asm volatile("cp.async.wait_group 1;" ::: "memory")

__device__ __forceinline__ void mma16816(float* c, const uint32_t* a, const uint32_t* b) {
    asm volatile(
        "mma.sync.aligned.m16n8k16.row.col.f32.f16.f16.f32 "
        "{%0,%1,%2,%3}, {%4,%5,%6,%7}, {%8,%9}, {%0,%1,%2,%3};"
        : "+f"(c[0]), "+f"(c[1]), "+f"(c[2]), "+f"(c[3])
        : "r"(a[0]), "r"(a[1]), "r"(a[2]), "r"(a[3]), "r"(b[0]), "r"(b[1]));
}
#define LDSM4(r, a)                                                             \
    asm volatile("ldmatrix.sync.aligned.m8n8.x4.shared.b16 {%0,%1,%2,%3}, [%4];" \
        : "=r"((r)[0]), "=r"((r)[1]), "=r"((r)[2]), "=r"((r)[3]) : "r"(a))

// ---------------------------------------------------------------------------
// Conversions for GEMM: A -> fp16 hi|lo (K=4096); W -> single fp16 transposed
// ---------------------------------------------------------------------------
__global__ __launch_bounds__(256) void convA2(const float* __restrict__ A,
                                              __half* __restrict__ A2)
{
    int idx = blockIdx.x * 256 + threadIdx.x;
    int m = idx >> 9;
    int j = (idx & 511) * 4;
    float4 v = *(const float4*)(A + (size_t)m * GK_ + j);
    float xs[4] = {v.x, v.y, v.z, v.w};
    __half h[4], l[4];
#pragma unroll
    for (int i = 0; i < 4; i++) {
        h[i] = __float2half_rn(xs[i]);
        l[i] = __float2half_rn(xs[i] - __half2float(h[i]));
    }
    size_t r = (size_t)m * GK2 + j;
    *(uint2*)&A2[r]       = *(uint2*)h;
    *(uint2*)&A2[r + GK_] = *(uint2*)l;
}

__global__ __launch_bounds__(256) void convW2(const float* __restrict__ W,
                                              __half* __restrict__ W2, int N)
{
    __shared__ float t[32][33];
    int n0 = blockIdx.x * 32, k0 = blockIdx.y * 32;
    int tx = threadIdx.x & 31, ty = threadIdx.x >> 5;
#pragma unroll
    for (int i = 0; i < 32; i += 8)
        t[ty + i][tx] = W[(size_t)(k0 + ty + i) * N + n0 + tx];
    __syncthreads();
#pragma unroll
    for (int i = 0; i < 32; i += 8) {
        int n = n0 + ty + i, k = k0 + tx;
        W2[(size_t)n * GK_ + k] = __float2half_rn(t[tx][ty + i]);
    }
}

// ---------------------------------------------------------------------------
// mma.sync fp16 GEMM: C[8192,Nn] = A2[8192,4096(hi|lo)] @ W2[Nn,2048]^T + bias
// (A k-segment >= 2048 multiplies the SAME W columns k-2048)
// ---------------------------------------------------------------------------
__global__ __launch_bounds__(256) void gemm_mma(
    const __half* __restrict__ A2, const __half* __restrict__ B2,
    const float* __restrict__ bias, float* __restrict__ C, int Nn)
{
    extern __shared__ __align__(16) char smraw[];
    __half* sA = (__half*)smraw;
    __half* sB = sA + NSTAGE * 128 * LDS_K;
    float* sbias = (float*)(sB + NSTAGE * 128 * LDS_K);

    const int tid = threadIdx.x;
    const int m0 = blockIdx.y * 128;
    const int n0 = blockIdx.x * 128;

    if (tid < 128) sbias[tid] = bias ? bias[n0 + tid] : 0.f;

    const int seg = tid & 7;
    const int r0  = tid >> 3;
    const __half* Ag = A2 + (size_t)m0 * GK2 + seg * 8;
    const __half* Bg = B2 + (size_t)n0 * GK_ + seg * 8;
    const uint32_t sAu = smem_u32(sA);
    const uint32_t sBu = smem_u32(sB);

#define LOAD_STAGE(chunk, st) do {                                              \
    int _k0 = (chunk) * KC;                                                     \
    int _k0b = _k0 & (GK_ - 1);                                                 \
    uint32_t _da = sAu + (uint32_t)(st) * 18432;                                \
    uint32_t _db = sBu + (uint32_t)(st) * 18432;                                \
    _Pragma("unroll")                                                           \
    for (int _rr = 0; _rr < 4; _rr++) {                                         \
        int _row = r0 + _rr * 32;                                               \
        uint32_t _o = (uint32_t)(_row * LDS_K + seg * 8) * 2;                   \
        cp16(_da + _o, Ag + (size_t)_row * GK2 + _k0);                          \
        cp16(_db + _o, Bg + (size_t)_row * GK_ + _k0b);                         \
    }                                                                           \
} while (0)

    const int wid = tid >> 5, lane = tid & 31;
    const int wm = (wid >> 2) * 64;
    const int wn = (wid & 3) * 32;
    const int g = lane >> 2, t = lane & 3;

    const uint32_t aOff = (uint32_t)((wm + (lane & 15)) * 144 + (lane >> 4) * 16);
    const uint32_t bOff = (uint32_t)((wn + ((lane >> 4) << 3) + (lane & 7)) * 144 +
                                     ((lane >> 3) & 1) * 16);

    float acc[4][4][4];
#pragma unroll
    for (int mi = 0; mi < 4; mi++)
#pragma unroll
        for (int ni = 0; ni < 4; ni++)
#pragma unroll
            for (int e = 0; e < 4; e++) acc[mi][ni][e] = 0.f;

    LOAD_STAGE(0, 0); CP_COMMIT();
    LOAD_STAGE(1, 1); CP_COMMIT();

    for (int c = 0; c < NC; c++) {
        CP_WAIT1();
        __syncthreads();

        int lc = c + 2;
        int st_ld = lc - (lc / 3) * 3;
        if (lc < NC) LOAD_STAGE(lc, st_ld);
        CP_COMMIT();

        int st = c - (c / 3) * 3;
        const uint32_t aS = sAu + st * 18432 + aOff;
        const uint32_t bS = sBu + st * 18432 + bOff;

#pragma unroll
        for (int ks = 0; ks < 4; ks++) {
            uint32_t af[4][4], bq[2][4];
#pragma unroll
            for (int mi = 0; mi < 4; mi++) LDSM4(af[mi], aS + mi * 2304 + ks * 32);
#pragma unroll
            for (int p = 0; p < 2; p++) LDSM4(bq[p], bS + p * 2304 + ks * 32);
#pragma unroll
            for (int mi = 0; mi < 4; mi++)
#pragma unroll
                for (int ni = 0; ni < 4; ni++)
                    mma16816(acc[mi][ni], af[mi], &bq[ni >> 1][(ni & 1) * 2]);
        }
    }

    __syncthreads();
#pragma unroll
    for (int mi = 0; mi < 4; mi++) {
        int row = m0 + wm + mi * 16 + g;
#pragma unroll
        for (int ni = 0; ni < 4; ni++) {
            int lcol = wn + ni * 8 + 2 * t;
            float b0 = sbias[lcol], b1 = sbias[lcol + 1];
            float2 v0 = {acc[mi][ni][0] + b0, acc[mi][ni][1] + b1};
            float2 v1 = {acc[mi][ni][2] + b0, acc[mi][ni][3] + b1};
            *(float2*)(C + (size_t)row * Nn + n0 + lcol) = v0;
            *(float2*)(C + (size_t)(row + 8) * Nn + n0 + lcol) = v1;
        }
    }
#undef LOAD_STAGE
}

// ---------------------------------------------------------------------------
// Fused RoPE + scale + fp16 conversion for Q (hi|lo) and K (single).
// ---------------------------------------------------------------------------
__global__ __launch_bounds__(256) void conv_qk(
    const float* __restrict__ q, const float* __restrict__ k,
    const int* __restrict__ positions,
    __half* __restrict__ Q2, __half* __restrict__ K2)
{
    int idx = blockIdx.x * 256 + threadIdx.x;   // 4*2048*12*32
    int dg = idx & 31;
    int r = idx >> 5;
    int head = r % 12;
    int bs = r / 12;
    int b = bs >> 11, s = bs & 2047;
    int pos = positions[bs];
    int d0 = dg * 4;

    const bool isq = head < NH_;
    const float* src;
    float sc;
    if (isq) {
        src = q + ((size_t)bs * NH_ + head) * HD_;
        sc = SCALE_;
    } else {
        src = k + ((size_t)bs * NKV_ + (head - NH_)) * HD_;
        sc = 1.0f;
    }
    float4 x1 = *(const float4*)(src + d0);
    float4 x2 = *(const float4*)(src + d0 + 128);
    float a1[4] = {x1.x, x1.y, x1.z, x1.w};
    float a2[4] = {x2.x, x2.y, x2.z, x2.w};
    float y1[4], y2[4];
#pragma unroll
    for (int e = 0; e < 4; e++) {
        int d = d0 + e;
        float inv_freq = powf(10000.0f, -(float)d * (1.0f / 128.0f));
        float fr = (float)pos * inv_freq;
        float sn, cs;
        sincosf(fr, &sn, &cs);
        y1[e] = (a1[e] * cs - a2[e] * sn) * sc;
        y2[e] = (a2[e] * cs + a1[e] * sn) * sc;
    }
    if (isq) {
        __half* dst = Q2 + ((size_t)(b * NH_ + head) * S_ + s) * 512;
        __half h1[4], l1[4], h2[4], l2[4];
#pragma unroll
        for (int e = 0; e < 4; e++) {
            h1[e] = __float2half_rn(y1[e]);
            l1[e] = __float2half_rn(y1[e] - __half2float(h1[e]));
            h2[e] = __float2half_rn(y2[e]);
            l2[e] = __float2half_rn(y2[e] - __half2float(h2[e]));
        }
        *(uint2*)(dst + d0)       = *(uint2*)h1;
        *(uint2*)(dst + 128 + d0) = *(uint2*)h2;
        *(uint2*)(dst + 256 + d0) = *(uint2*)l1;
        *(uint2*)(dst + 384 + d0) = *(uint2*)l2;
    } else {
        __half* dst = K2 + ((size_t)(b * NKV_ + head - NH_) * S_ + s) * 256;
        __half h1[4], h2[4];
#pragma unroll
        for (int e = 0; e < 4; e++) {
            h1[e] = __float2half_rn(y1[e]);
            h2[e] = __float2half_rn(y2[e]);
        }
        *(uint2*)(dst + d0)       = *(uint2*)h1;
        *(uint2*)(dst + 128 + d0) = *(uint2*)h2;
    }
}

// ---------------------------------------------------------------------------
// V transpose + single fp16: g_v [b][s][kvh][256] -> g_vt [b][kvh][256][S]
// ---------------------------------------------------------------------------
__global__ __launch_bounds__(256) void conv_v(const float* __restrict__ v,
                                              __half* __restrict__ Vt)
{
    __shared__ float tile[32][33];
    int s0 = blockIdx.x * 32, d0 = blockIdx.y * 32;
    int b = blockIdx.z >> 2, kvh = blockIdx.z & 3;
    int tx = threadIdx.x & 31, ty = threadIdx.x >> 5;
#pragma unroll
    for (int i = 0; i < 32; i += 8)
        tile[ty + i][tx] = v[((size_t)(b * S_ + s0 + ty + i) * NKV_ + kvh) * HD_ + d0 + tx];
    __syncthreads();
    size_t base = (size_t)(b * NKV_ + kvh) * 256;
#pragma unroll
    for (int i = 0; i < 32; i += 8) {
        int d = d0 + ty + i;
        Vt[(base + d) * S_ + s0 + tx] = __float2half_rn(tile[tx][ty + i]);
    }
}

// ---------------------------------------------------------------------------
// Tensor-core sliding-window flash attention (fp16).
// QK: 2 passes (qh*k + ql*k). PV: 2 mmas (ph*v + pl*v).
// ---------------------------------------------------------------------------
#define QLD 520      // fp16 elems per Q smem row (512 + 8 pad)
#define KLD 264      // fp16 elems per K smem row (256 + 8 pad)
#define VLD 40       // fp16 elems per V smem row (32 + 8 pad)

__global__ __launch_bounds__(256, 1) void attn_mma(
    const __half* __restrict__ Q2, const __half* __restrict__ K2,
    const __half* __restrict__ Vt, float* __restrict__ Og)
{
    extern __shared__ __align__(16) __half smb[];
    __half* Qs = smb;                 // [128][520]
    __half* Ks = Qs + 128 * QLD;      // [32][264]
    __half* Vs = Ks + 32 * KLD;       // [256][40]

    const int tid = threadIdx.x;
    const int w = tid >> 5, lane = tid & 31;
    const int g = lane >> 2, t = lane & 3;
    const int q0 = blockIdx.x * 128;
    const int h = blockIdx.y;
    const int b = blockIdx.z;
    const int kvh = h >> 1;

    const uint32_t QsA = smem_u32(Qs);
    const uint32_t KsA = smem_u32(Ks);
    const uint32_t VsA = smem_u32(Vs);

    const __half* Qg = Q2 + ((size_t)(b * NH_ + h) * S_ + q0) * 512;
    const __half* Kg = K2 + (size_t)(b * NKV_ + kvh) * S_ * 256;
    const __half* Vg = Vt + (size_t)(b * NKV_ + kvh) * 256 * S_;

    const uint32_t qA = QsA + (uint32_t)((w * 16 + (lane & 15)) * QLD * 2 + (lane >> 4) * 16);
    const uint32_t kB = KsA + (uint32_t)((((lane >> 4) << 3) + (lane & 7)) * KLD * 2 +
                                         ((lane >> 3) & 1) * 16);
    const uint32_t vB = VsA + (uint32_t)((((lane >> 4) << 3) + (lane & 7)) * VLD * 2 +
                                         ((lane >> 3) & 1) * 16);

    // ---- load Q tile
#pragma unroll
    for (int it = 0; it < 32; it++) {
        int idx = tid + it * 256;
        int r = idx >> 6, seg = idx & 63;
        cp16(QsA + (uint32_t)(r * QLD + seg * 8) * 2, Qg + (size_t)r * 512 + seg * 8);
    }
    CP_COMMIT();

    int lo = q0 - (WIN_ - 1); if (lo < 0) lo = 0;
    const int kt0 = (lo >> 5) << 5;
    const int ntiles = ((q0 + 96) - kt0) / 32 + 1;

#define LOAD_K(kt) do {                                                         \
    _Pragma("unroll")                                                           \
    for (int _it = 0; _it < 4; _it++) {                                         \
        int _i = tid + _it * 256;                                               \
        int _r = _i >> 5, _sg = _i & 31;                                        \
        cp16(KsA + (uint32_t)(_r * KLD + _sg * 8) * 2,                          \
             Kg + ((size_t)((kt) + _r)) * 256 + _sg * 8);                       \
    }                                                                           \
} while (0)
#define LOAD_V(kt) do {                                                         \
    _Pragma("unroll")                                                           \
    for (int _it = 0; _it < 4; _it++) {                                         \
        int _i = tid + _it * 256;                                               \
        int _r = _i >> 2, _sg = _i & 3;                                         \
        cp16(VsA + (uint32_t)(_r * VLD + _sg * 8) * 2,                          \
             Vg + (size_t)_r * S_ + (kt) + _sg * 8);                            \
    }                                                                           \
} while (0)

    LOAD_K(kt0); CP_COMMIT();
    LOAD_V(kt0); CP_COMMIT();

    float o[32][4];
#pragma unroll
    for (int nt = 0; nt < 32; nt++)
#pragma unroll
        for (int e = 0; e < 4; e++) o[nt][e] = 0.f;
    float rmax0 = -1e20f, rmax1 = -1e20f, rsum0 = 0.f, rsum1 = 0.f;

    const int rmin = q0 + w * 16;
    const int rmax_w = rmin + 15;
    const int row0 = rmin + g;
    const int row1 = row0 + 8;
    const int tcol = 2 * t;

    for (int j = 0; j < ntiles; j++) {
        const int kt = kt0 + 32 * j;
        const bool skipT = (kt > rmax_w) || (kt + 31 < rmin - (WIN_ - 1));
        const bool edge = !((kt + 31 <= rmin) && (kt >= rmax_w - (WIN_ - 1)));

        CP_WAIT1();
        __syncthreads();

        float s[4][4];
        if (!skipT) {
#pragma unroll
            for (int nt = 0; nt < 4; nt++)
#pragma unroll
                for (int e = 0; e < 4; e++) s[nt][e] = 0.f;
#pragma unroll
            for (int pass = 0; pass < 2; pass++) {
                uint32_t qb = qA + (uint32_t)(pass * 512);   // lo half at elem 256
#pragma unroll 4
                for (int ks = 0; ks < 16; ks++) {
                    uint32_t a[4], b0[4], b1[4];
                    LDSM4(a, qb + ks * 32);
                    LDSM4(b0, kB + ks * 32);
                    LDSM4(b1, kB + 16 * KLD * 2 + ks * 32);
                    mma16816(s[0], a, &b0[0]);
                    mma16816(s[1], a, &b0[2]);
                    mma16816(s[2], a, &b1[0]);
                    mma16816(s[3], a, &b1[2]);
                }
            }
        }
        __syncthreads();
        if (j + 1 < ntiles) LOAD_K(kt + 32);
        CP_COMMIT();
        CP_WAIT1();
        __syncthreads();

        if (!skipT) {
            if (edge) {
#pragma unroll
                for (int nt = 0; nt < 4; nt++) {
                    int c0 = kt + nt * 8 + tcol, c1 = c0 + 1;
                    if (!(c0 <= row0 && c0 > row0 - WIN_)) s[nt][0] = -1e30f;
                    if (!(c1 <= row0 && c1 > row0 - WIN_)) s[nt][1] = -1e30f;
                    if (!(c0 <= row1 && c0 > row1 - WIN_)) s[nt][2] = -1e30f;
                    if (!(c1 <= row1 && c1 > row1 - WIN_)) s[nt][3] = -1e30f;
                }
            }
            float m0 = fmaxf(fmaxf(s[0][0], s[0][1]), fmaxf(s[1][0], s[1][1]));
            m0 = fmaxf(m0, fmaxf(fmaxf(s[2][0], s[2][1]), fmaxf(s[3][0], s[3][1])));
            float m1 = fmaxf(fmaxf(s[0][2], s[0][3]), fmaxf(s[1][2], s[1][3]));
            m1 = fmaxf(m1, fmaxf(fmaxf(s[2][2], s[2][3]), fmaxf(s[3][2], s[3][3])));
            m0 = fmaxf(m0, __shfl_xor_sync(0xffffffffu, m0, 1));
            m0 = fmaxf(m0, __shfl_xor_sync(0xffffffffu, m0, 2));
            m1 = fmaxf(m1, __shfl_xor_sync(0xffffffffu, m1, 1));
            m1 = fmaxf(m1, __shfl_xor_sync(0xffffffffu, m1, 2));
            float nm0 = fmaxf(rmax0, m0), nm1 = fmaxf(rmax1, m1);
            float al0 = __expf(rmax0 - nm0), al1 = __expf(rmax1 - nm1);
            float ls0 = 0.f, ls1 = 0.f;
#pragma unroll
            for (int nt = 0; nt < 4; nt++) {
                s[nt][0] = __expf(s[nt][0] - nm0);
                s[nt][1] = __expf(s[nt][1] - nm0);
                s[nt][2] = __expf(s[nt][2] - nm1);
                s[nt][3] = __expf(s[nt][3] - nm1);
                ls0 += s[nt][0] + s[nt][1];
                ls1 += s[nt][2] + s[nt][3];
            }
            ls0 += __shfl_xor_sync(0xffffffffu, ls0, 1);
            ls0 += __shfl_xor_sync(0xffffffffu, ls0, 2);
            ls1 += __shfl_xor_sync(0xffffffffu, ls1, 1);
            ls1 += __shfl_xor_sync(0xffffffffu, ls1, 2);
            rsum0 = rsum0 * al0 + ls0;
            rsum1 = rsum1 * al1 + ls1;
            rmax0 = nm0; rmax1 = nm1;
#pragma unroll
            for (int nt = 0; nt < 32; nt++) {
                o[nt][0] *= al0; o[nt][1] *= al0;
                o[nt][2] *= al1; o[nt][3] *= al1;
            }
            // pack P hi/lo (fp16)
            uint32_t ph[4][2], pl[4][2];
#pragma unroll
            for (int nt = 0; nt < 4; nt++) {
                __half2 h01 = __floats2half2_rn(s[nt][0], s[nt][1]);
                __half2 h23 = __floats2half2_rn(s[nt][2], s[nt][3]);
                ph[nt][0] = *(uint32_t*)&h01;
                ph[nt][1] = *(uint32_t*)&h23;
                __half2 l01 = __floats2half2_rn(s[nt][0] - __low2float(h01),
                                                s[nt][1] - __high2float(h01));
                __half2 l23 = __floats2half2_rn(s[nt][2] - __low2float(h23),
                                                s[nt][3] - __high2float(h23));
                pl[nt][0] = *(uint32_t*)&l01;
                pl[nt][1] = *(uint32_t*)&l23;
            }
#pragma unroll
            for (int kk = 0; kk < 2; kk++) {
                uint32_t Ah[4] = {ph[2 * kk][0], ph[2 * kk][1], ph[2 * kk + 1][0], ph[2 * kk + 1][1]};
                uint32_t Al[4] = {pl[2 * kk][0], pl[2 * kk][1], pl[2 * kk + 1][0], pl[2 * kk + 1][1]};
#pragma unroll
                for (int p = 0; p < 16; p++) {
                    uint32_t rv[4];
                    LDSM4(rv, vB + p * (16 * VLD * 2) + kk * 32);
                    mma16816(o[2 * p], Ah, &rv[0]);
                    mma16816(o[2 * p], Al, &rv[0]);
                    mma16816(o[2 * p + 1], Ah, &rv[2]);
                    mma16816(o[2 * p + 1], Al, &rv[2]);
                }
            }
        }
        __syncthreads();
        if (j + 1 < ntiles) LOAD_V(kt + 32);
        CP_COMMIT();
    }

    float inv0 = 1.0f / rsum0, inv1 = 1.0f / rsum1;
    float* d0p = Og + ((size_t)(b * S_ + row0) * NH_ + h) * HD_;
    float* d1p = Og + ((size_t)(b * S_ + row1) * NH_ + h) * HD_;
#pragma unroll
    for (int nt = 0; nt < 32; nt++) {
        int d = nt * 8 + tcol;
        float2 v0 = {o[nt][0] * inv0, o[nt][1] * inv0};
        float2 v1 = {o[nt][2] * inv1, o[nt][3] * inv1};
        *(float2*)(d0p + d) = v0;
        *(float2*)(d1p + d) = v1;
    }
#undef LOAD_K
#undef LOAD_V
}

// ---------------------------------------------------------------------------
// Launch
// ---------------------------------------------------------------------------
extern "C" void kernel_launch(void* const* d_in, const int* in_sizes, int n_in,
                              void* d_out, int out_size)
{
    const float* hidden    = (const float*)d_in[0];
    const int*   positions = (const int*)d_in[1];
    const float* Wq        = (const float*)d_in[2];
    const float* bq        = (const float*)d_in[3];
    const float* Wk        = (const float*)d_in[4];
    const float* bk        = (const float*)d_in[5];
    const float* Wv        = (const float*)d_in[6];
    const float* bv        = (const float*)d_in[7];
    const float* Wo        = (const float*)d_in[8];
    float* out = (float*)d_out;

    float *qp, *kp, *vp, *ap;
    __half *a2, *w2, *q2, *k2, *vt;
    cudaGetSymbolAddress((void**)&qp, g_q);
    cudaGetSymbolAddress((void**)&kp, g_k);
    cudaGetSymbolAddress((void**)&vp, g_v);
    cudaGetSymbolAddress((void**)&ap, g_attn);
    cudaGetSymbolAddress((void**)&a2, g_a2);
    cudaGetSymbolAddress((void**)&w2, g_w2);
    cudaGetSymbolAddress((void**)&q2, g_q2);
    cudaGetSymbolAddress((void**)&k2, g_k2);
    cudaGetSymbolAddress((void**)&vt, g_vt);

    const int M = B_ * S_;
    const size_t gemm_smem = (size_t)NSTAGE * 128 * LDS_K * 2 * 2 + 512;
    cudaFuncSetAttribute(gemm_mma, cudaFuncAttributeMaxDynamicSharedMemorySize, (int)gemm_smem);

    convA2<<<M * 512 / 256, 256>>>(hidden, a2);

    convW2<<<dim3(2048 / 32, 64), 256>>>(Wq, w2, 2048);
    gemm_mma<<<dim3(16, 64), 256, gemm_smem>>>(a2, w2, bq, qp, 2048);
    convW2<<<dim3(1024 / 32, 64), 256>>>(Wk, w2, 1024);
    gemm_mma<<<dim3(8, 64), 256, gemm_smem>>>(a2, w2, bk, kp, 1024);
    convW2<<<dim3(1024 / 32, 64), 256>>>(Wv, w2, 1024);
    gemm_mma<<<dim3(8, 64), 256, gemm_smem>>>(a2, w2, bv, vp, 1024);

    conv_qk<<<(B_ * S_ * 12 * 32) / 256, 256>>>(qp, kp, positions, q2, k2);
    conv_v<<<dim3(S_ / 32, HD_ / 32, B_ * NKV_), 256>>>(vp, vt);

    {
        size_t smem = (size_t)(128 * QLD + 32 * KLD + 256 * VLD) * 2;  // 170,496 B
        cudaFuncSetAttribute(attn_mma, cudaFuncAttributeMaxDynamicSharedMemorySize, (int)smem);
        attn_mma<<<dim3(S_ / 128, NH_, B_), 256, smem>>>(q2, k2, vt, ap);
    }

    convA2<<<M * 512 / 256, 256>>>(ap, a2);
    convW2<<<dim3(2048 / 32, 64), 256>>>(Wo, w2, 2048);
    gemm_mma<<<dim3(16, 64), 256, gemm_smem>>>(a2, w2, nullptr, out, 2048);
}

// round 6
// speedup vs baseline: 5.9009x; 1.2962x over previous
#include <cuda_runtime.h>
#include <cuda_fp16.h>
#include <math.h>
#include <stdint.h>

// Problem constants (Gemma2 attention layer)
#define B_ 4
#define S_ 2048
#define H_ 2048
#define NH_ 8
#define NKV_ 4
#define HD_ 256
#define WIN_ 1024
#define SCALE_ 0.0625f   // 256^-0.5

#define GK_   2048       // inner K of every GEMM
#define GK2   4096       // 2x split K (A = hi|lo)
#define KC    64         // K-chunk per pipeline stage
#define NSTAGE 3
#define LDS_K 72         // padded smem k-stride (fp16 elems), 144B rows

// ---------------------------------------------------------------------------
// Scratch (device globals — no allocation allowed)
// ---------------------------------------------------------------------------
__device__ float g_q[(size_t)B_ * S_ * NH_ * HD_];
__device__ float g_k[(size_t)B_ * S_ * NKV_ * HD_];
__device__ float g_v[(size_t)B_ * S_ * NKV_ * HD_];
__device__ __half g_a2[(size_t)B_ * S_ * GK2];                // 64 MB (hi|lo)
__device__ __half g_w2[(size_t)H_ * GK_];                     // 8 MB (single fp16)
// attention operands
__device__ __half g_q2[(size_t)B_ * NH_ * S_ * 512];          // [b][h][s][qhi(256)|qlo(256)]
__device__ __half g_k2[(size_t)B_ * NKV_ * S_ * 256];         // [b][kvh][s][khi(256)]
__device__ __half g_vt[(size_t)B_ * NKV_ * 256 * S_];         // [b][kvh][d(256)][s]

// ---------------------------------------------------------------------------
// Helpers
// ---------------------------------------------------------------------------
__device__ __forceinline__ uint32_t smem_u32(const void* p) {
    uint32_t a;
    asm("{ .reg .u64 t; cvta.to.shared.u64 t, %1; cvt.u32.u64 %0, t; }" : "=r"(a) : "l"(p));
    return a;
}
__device__ __forceinline__ void cp16(uint32_t dst, const void* src) {
    asm volatile("cp.async.cg.shared.global [%0], [%1], 16;" :: "r"(dst), "l"(src));
}
#define CP_COMMIT() asm volatile("cp.async.commit_group;" ::: "memory")
#define CP_WAIT1()  asm volatile("cp.async.wait_group 1;" ::: "memory")

__device__ __forceinline__ void mma16816(float* c, const uint32_t* a, const uint32_t* b) {
    asm volatile(
        "mma.sync.aligned.m16n8k16.row.col.f32.f16.f16.f32 "
        "{%0,%1,%2,%3}, {%4,%5,%6,%7}, {%8,%9}, {%0,%1,%2,%3};"
        : "+f"(c[0]), "+f"(c[1]), "+f"(c[2]), "+f"(c[3])
        : "r"(a[0]), "r"(a[1]), "r"(a[2]), "r"(a[3]), "r"(b[0]), "r"(b[1]));
}
#define LDSM4(r, a)                                                             \
    asm volatile("ldmatrix.sync.aligned.m8n8.x4.shared.b16 {%0,%1,%2,%3}, [%4];" \
        : "=r"((r)[0]), "=r"((r)[1]), "=r"((r)[2]), "=r"((r)[3]) : "r"(a))

// ---------------------------------------------------------------------------
// Conversions for GEMM: A -> fp16 hi|lo (K=4096); W -> single fp16 transposed
// ---------------------------------------------------------------------------
__global__ __launch_bounds__(256) void convA2(const float* __restrict__ A,
                                              __half* __restrict__ A2)
{
    int idx = blockIdx.x * 256 + threadIdx.x;
    int m = idx >> 9;
    int j = (idx & 511) * 4;
    float4 v = *(const float4*)(A + (size_t)m * GK_ + j);
    float xs[4] = {v.x, v.y, v.z, v.w};
    __half h[4], l[4];
#pragma unroll
    for (int i = 0; i < 4; i++) {
        h[i] = __float2half_rn(xs[i]);
        l[i] = __float2half_rn(xs[i] - __half2float(h[i]));
    }
    size_t r = (size_t)m * GK2 + j;
    *(uint2*)&A2[r]       = *(uint2*)h;
    *(uint2*)&A2[r + GK_] = *(uint2*)l;
}

__global__ __launch_bounds__(256) void convW2(const float* __restrict__ W,
                                              __half* __restrict__ W2, int N)
{
    __shared__ float t[32][33];
    int n0 = blockIdx.x * 32, k0 = blockIdx.y * 32;
    int tx = threadIdx.x & 31, ty = threadIdx.x >> 5;
#pragma unroll
    for (int i = 0; i < 32; i += 8)
        t[ty + i][tx] = W[(size_t)(k0 + ty + i) * N + n0 + tx];
    __syncthreads();
#pragma unroll
    for (int i = 0; i < 32; i += 8) {
        int n = n0 + ty + i, k = k0 + tx;
        W2[(size_t)n * GK_ + k] = __float2half_rn(t[tx][ty + i]);
    }
}

// ---------------------------------------------------------------------------
// mma.sync fp16 GEMM: C[8192,Nn] = A2[8192, nchunks*64] @ W2[Nn,2048]^T + bias
// nchunks=64: 2-term split-A (hi|lo); nchunks=32: single-term (hi only).
// ---------------------------------------------------------------------------
__global__ __launch_bounds__(256) void gemm_mma(
    const __half* __restrict__ A2, const __half* __restrict__ B2,
    const float* __restrict__ bias, float* __restrict__ C, int Nn, int nchunks)
{
    extern __shared__ __align__(16) char smraw[];
    __half* sA = (__half*)smraw;
    __half* sB = sA + NSTAGE * 128 * LDS_K;
    float* sbias = (float*)(sB + NSTAGE * 128 * LDS_K);

    const int tid = threadIdx.x;
    const int m0 = blockIdx.y * 128;
    const int n0 = blockIdx.x * 128;

    if (tid < 128) sbias[tid] = bias ? bias[n0 + tid] : 0.f;

    const int seg = tid & 7;
    const int r0  = tid >> 3;
    const __half* Ag = A2 + (size_t)m0 * GK2 + seg * 8;
    const __half* Bg = B2 + (size_t)n0 * GK_ + seg * 8;
    const uint32_t sAu = smem_u32(sA);
    const uint32_t sBu = smem_u32(sB);

#define LOAD_STAGE(chunk, st) do {                                              \
    int _k0 = (chunk) * KC;                                                     \
    int _k0b = _k0 & (GK_ - 1);                                                 \
    uint32_t _da = sAu + (uint32_t)(st) * 18432;                                \
    uint32_t _db = sBu + (uint32_t)(st) * 18432;                                \
    _Pragma("unroll")                                                           \
    for (int _rr = 0; _rr < 4; _rr++) {                                         \
        int _row = r0 + _rr * 32;                                               \
        uint32_t _o = (uint32_t)(_row * LDS_K + seg * 8) * 2;                   \
        cp16(_da + _o, Ag + (size_t)_row * GK2 + _k0);                          \
        cp16(_db + _o, Bg + (size_t)_row * GK_ + _k0b);                         \
    }                                                                           \
} while (0)

    const int wid = tid >> 5, lane = tid & 31;
    const int wm = (wid >> 2) * 64;
    const int wn = (wid & 3) * 32;
    const int g = lane >> 2, t = lane & 3;

    const uint32_t aOff = (uint32_t)((wm + (lane & 15)) * 144 + (lane >> 4) * 16);
    const uint32_t bOff = (uint32_t)((wn + ((lane >> 4) << 3) + (lane & 7)) * 144 +
                                     ((lane >> 3) & 1) * 16);

    float acc[4][4][4];
#pragma unroll
    for (int mi = 0; mi < 4; mi++)
#pragma unroll
        for (int ni = 0; ni < 4; ni++)
#pragma unroll
            for (int e = 0; e < 4; e++) acc[mi][ni][e] = 0.f;

    LOAD_STAGE(0, 0); CP_COMMIT();
    LOAD_STAGE(1, 1); CP_COMMIT();

    for (int c = 0; c < nchunks; c++) {
        CP_WAIT1();
        __syncthreads();

        int lc = c + 2;
        int st_ld = lc - (lc / 3) * 3;
        if (lc < nchunks) LOAD_STAGE(lc, st_ld);
        CP_COMMIT();

        int st = c - (c / 3) * 3;
        const uint32_t aS = sAu + st * 18432 + aOff;
        const uint32_t bS = sBu + st * 18432 + bOff;

#pragma unroll
        for (int ks = 0; ks < 4; ks++) {
            uint32_t af[4][4], bq[2][4];
#pragma unroll
            for (int mi = 0; mi < 4; mi++) LDSM4(af[mi], aS + mi * 2304 + ks * 32);
#pragma unroll
            for (int p = 0; p < 2; p++) LDSM4(bq[p], bS + p * 2304 + ks * 32);
#pragma unroll
            for (int mi = 0; mi < 4; mi++)
#pragma unroll
                for (int ni = 0; ni < 4; ni++)
                    mma16816(acc[mi][ni], af[mi], &bq[ni >> 1][(ni & 1) * 2]);
        }
    }

    __syncthreads();
#pragma unroll
    for (int mi = 0; mi < 4; mi++) {
        int row = m0 + wm + mi * 16 + g;
#pragma unroll
        for (int ni = 0; ni < 4; ni++) {
            int lcol = wn + ni * 8 + 2 * t;
            float b0 = sbias[lcol], b1 = sbias[lcol + 1];
            float2 v0 = {acc[mi][ni][0] + b0, acc[mi][ni][1] + b1};
            float2 v1 = {acc[mi][ni][2] + b0, acc[mi][ni][3] + b1};
            *(float2*)(C + (size_t)row * Nn + n0 + lcol) = v0;
            *(float2*)(C + (size_t)(row + 8) * Nn + n0 + lcol) = v1;
        }
    }
#undef LOAD_STAGE
}

// ---------------------------------------------------------------------------
// Fused RoPE + scale + fp16 conversion for Q (hi|lo) and K (single).
// ---------------------------------------------------------------------------
__global__ __launch_bounds__(256) void conv_qk(
    const float* __restrict__ q, const float* __restrict__ k,
    const int* __restrict__ positions,
    __half* __restrict__ Q2, __half* __restrict__ K2)
{
    int idx = blockIdx.x * 256 + threadIdx.x;   // 4*2048*12*32
    int dg = idx & 31;
    int r = idx >> 5;
    int head = r % 12;
    int bs = r / 12;
    int b = bs >> 11, s = bs & 2047;
    int pos = positions[bs];
    int d0 = dg * 4;

    const bool isq = head < NH_;
    const float* src;
    float sc;
    if (isq) {
        src = q + ((size_t)bs * NH_ + head) * HD_;
        sc = SCALE_;
    } else {
        src = k + ((size_t)bs * NKV_ + (head - NH_)) * HD_;
        sc = 1.0f;
    }
    float4 x1 = *(const float4*)(src + d0);
    float4 x2 = *(const float4*)(src + d0 + 128);
    float a1[4] = {x1.x, x1.y, x1.z, x1.w};
    float a2[4] = {x2.x, x2.y, x2.z, x2.w};
    float y1[4], y2[4];
#pragma unroll
    for (int e = 0; e < 4; e++) {
        int d = d0 + e;
        float inv_freq = powf(10000.0f, -(float)d * (1.0f / 128.0f));
        float fr = (float)pos * inv_freq;
        float sn, cs;
        sincosf(fr, &sn, &cs);
        y1[e] = (a1[e] * cs - a2[e] * sn) * sc;
        y2[e] = (a2[e] * cs + a1[e] * sn) * sc;
    }
    if (isq) {
        __half* dst = Q2 + ((size_t)(b * NH_ + head) * S_ + s) * 512;
        __half h1[4], l1[4], h2[4], l2[4];
#pragma unroll
        for (int e = 0; e < 4; e++) {
            h1[e] = __float2half_rn(y1[e]);
            l1[e] = __float2half_rn(y1[e] - __half2float(h1[e]));
            h2[e] = __float2half_rn(y2[e]);
            l2[e] = __float2half_rn(y2[e] - __half2float(h2[e]));
        }
        *(uint2*)(dst + d0)       = *(uint2*)h1;
        *(uint2*)(dst + 128 + d0) = *(uint2*)h2;
        *(uint2*)(dst + 256 + d0) = *(uint2*)l1;
        *(uint2*)(dst + 384 + d0) = *(uint2*)l2;
    } else {
        __half* dst = K2 + ((size_t)(b * NKV_ + head - NH_) * S_ + s) * 256;
        __half h1[4], h2[4];
#pragma unroll
        for (int e = 0; e < 4; e++) {
            h1[e] = __float2half_rn(y1[e]);
            h2[e] = __float2half_rn(y2[e]);
        }
        *(uint2*)(dst + d0)       = *(uint2*)h1;
        *(uint2*)(dst + 128 + d0) = *(uint2*)h2;
    }
}

// ---------------------------------------------------------------------------
// V transpose + single fp16: g_v [b][s][kvh][256] -> g_vt [b][kvh][256][S]
// ---------------------------------------------------------------------------
__global__ __launch_bounds__(256) void conv_v(const float* __restrict__ v,
                                              __half* __restrict__ Vt)
{
    __shared__ float tile[32][33];
    int s0 = blockIdx.x * 32, d0 = blockIdx.y * 32;
    int b = blockIdx.z >> 2, kvh = blockIdx.z & 3;
    int tx = threadIdx.x & 31, ty = threadIdx.x >> 5;
#pragma unroll
    for (int i = 0; i < 32; i += 8)
        tile[ty + i][tx] = v[((size_t)(b * S_ + s0 + ty + i) * NKV_ + kvh) * HD_ + d0 + tx];
    __syncthreads();
    size_t base = (size_t)(b * NKV_ + kvh) * 256;
#pragma unroll
    for (int i = 0; i < 32; i += 8) {
        int d = d0 + ty + i;
        Vt[(base + d) * S_ + s0 + tx] = __float2half_rn(tile[tx][ty + i]);
    }
}

// ---------------------------------------------------------------------------
// Tensor-core sliding-window flash attention (fp16).
// QK: 2 passes (qh*k + ql*k). PV: 2 mmas (ph*v + pl*v).
// Epilogue writes fp16 directly into A2 (hi region) for the O projection.
// ---------------------------------------------------------------------------
#define QLD 520      // fp16 elems per Q smem row (512 + 8 pad)
#define KLD 264      // fp16 elems per K smem row (256 + 8 pad)
#define VLD 40       // fp16 elems per V smem row (32 + 8 pad)

__global__ __launch_bounds__(256, 1) void attn_mma(
    const __half* __restrict__ Q2, const __half* __restrict__ K2,
    const __half* __restrict__ Vt, __half* __restrict__ A2out)
{
    extern __shared__ __align__(16) __half smb[];
    __half* Qs = smb;                 // [128][520]
    __half* Ks = Qs + 128 * QLD;      // [32][264]
    __half* Vs = Ks + 32 * KLD;       // [256][40]

    const int tid = threadIdx.x;
    const int w = tid >> 5, lane = tid & 31;
    const int g = lane >> 2, t = lane & 3;
    const int q0 = blockIdx.x * 128;
    const int h = blockIdx.y;
    const int b = blockIdx.z;
    const int kvh = h >> 1;

    const uint32_t QsA = smem_u32(Qs);
    const uint32_t KsA = smem_u32(Ks);
    const uint32_t VsA = smem_u32(Vs);

    const __half* Qg = Q2 + ((size_t)(b * NH_ + h) * S_ + q0) * 512;
    const __half* Kg = K2 + (size_t)(b * NKV_ + kvh) * S_ * 256;
    const __half* Vg = Vt + (size_t)(b * NKV_ + kvh) * 256 * S_;

    const uint32_t qA = QsA + (uint32_t)((w * 16 + (lane & 15)) * QLD * 2 + (lane >> 4) * 16);
    const uint32_t kB = KsA + (uint32_t)((((lane >> 4) << 3) + (lane & 7)) * KLD * 2 +
                                         ((lane >> 3) & 1) * 16);
    const uint32_t vB = VsA + (uint32_t)((((lane >> 4) << 3) + (lane & 7)) * VLD * 2 +
                                         ((lane >> 3) & 1) * 16);

    // ---- load Q tile
#pragma unroll
    for (int it = 0; it < 32; it++) {
        int idx = tid + it * 256;
        int r = idx >> 6, seg = idx & 63;
        cp16(QsA + (uint32_t)(r * QLD + seg * 8) * 2, Qg + (size_t)r * 512 + seg * 8);
    }
    CP_COMMIT();

    int lo = q0 - (WIN_ - 1); if (lo < 0) lo = 0;
    const int kt0 = (lo >> 5) << 5;
    const int ntiles = ((q0 + 96) - kt0) / 32 + 1;

#define LOAD_K(kt) do {                                                         \
    _Pragma("unroll")                                                           \
    for (int _it = 0; _it < 4; _it++) {                                         \
        int _i = tid + _it * 256;                                               \
        int _r = _i >> 5, _sg = _i & 31;                                        \
        cp16(KsA + (uint32_t)(_r * KLD + _sg * 8) * 2,                          \
             Kg + ((size_t)((kt) + _r)) * 256 + _sg * 8);                       \
    }                                                                           \
} while (0)
#define LOAD_V(kt) do {                                                         \
    _Pragma("unroll")                                                           \
    for (int _it = 0; _it < 4; _it++) {                                         \
        int _i = tid + _it * 256;                                               \
        int _r = _i >> 2, _sg = _i & 3;                                         \
        cp16(VsA + (uint32_t)(_r * VLD + _sg * 8) * 2,                          \
             Vg + (size_t)_r * S_ + (kt) + _sg * 8);                            \
    }                                                                           \
} while (0)

    LOAD_K(kt0); CP_COMMIT();
    LOAD_V(kt0); CP_COMMIT();

    float o[32][4];
#pragma unroll
    for (int nt = 0; nt < 32; nt++)
#pragma unroll
        for (int e = 0; e < 4; e++) o[nt][e] = 0.f;
    float rmax0 = -1e20f, rmax1 = -1e20f, rsum0 = 0.f, rsum1 = 0.f;

    const int rmin = q0 + w * 16;
    const int rmax_w = rmin + 15;
    const int row0 = rmin + g;
    const int row1 = row0 + 8;
    const int tcol = 2 * t;

    for (int j = 0; j < ntiles; j++) {
        const int kt = kt0 + 32 * j;
        const bool skipT = (kt > rmax_w) || (kt + 31 < rmin - (WIN_ - 1));
        const bool edge = !((kt + 31 <= rmin) && (kt >= rmax_w - (WIN_ - 1)));

        CP_WAIT1();
        __syncthreads();

        float s[4][4];
        if (!skipT) {
#pragma unroll
            for (int nt = 0; nt < 4; nt++)
#pragma unroll
                for (int e = 0; e < 4; e++) s[nt][e] = 0.f;
#pragma unroll
            for (int pass = 0; pass < 2; pass++) {
                uint32_t qb = qA + (uint32_t)(pass * 512);   // lo half at elem 256
#pragma unroll 4
                for (int ks = 0; ks < 16; ks++) {
                    uint32_t a[4], b0[4], b1[4];
                    LDSM4(a, qb + ks * 32);
                    LDSM4(b0, kB + ks * 32);
                    LDSM4(b1, kB + 16 * KLD * 2 + ks * 32);
                    mma16816(s[0], a, &b0[0]);
                    mma16816(s[1], a, &b0[2]);
                    mma16816(s[2], a, &b1[0]);
                    mma16816(s[3], a, &b1[2]);
                }
            }
        }
        __syncthreads();
        if (j + 1 < ntiles) LOAD_K(kt + 32);
        CP_COMMIT();
        CP_WAIT1();
        __syncthreads();

        if (!skipT) {
            if (edge) {
#pragma unroll
                for (int nt = 0; nt < 4; nt++) {
                    int c0 = kt + nt * 8 + tcol, c1 = c0 + 1;
                    if (!(c0 <= row0 && c0 > row0 - WIN_)) s[nt][0] = -1e30f;
                    if (!(c1 <= row0 && c1 > row0 - WIN_)) s[nt][1] = -1e30f;
                    if (!(c0 <= row1 && c0 > row1 - WIN_)) s[nt][2] = -1e30f;
                    if (!(c1 <= row1 && c1 > row1 - WIN_)) s[nt][3] = -1e30f;
                }
            }
            float m0 = fmaxf(fmaxf(s[0][0], s[0][1]), fmaxf(s[1][0], s[1][1]));
            m0 = fmaxf(m0, fmaxf(fmaxf(s[2][0], s[2][1]), fmaxf(s[3][0], s[3][1])));
            float m1 = fmaxf(fmaxf(s[0][2], s[0][3]), fmaxf(s[1][2], s[1][3]));
            m1 = fmaxf(m1, fmaxf(fmaxf(s[2][2], s[2][3]), fmaxf(s[3][2], s[3][3])));
            m0 = fmaxf(m0, __shfl_xor_sync(0xffffffffu, m0, 1));
            m0 = fmaxf(m0, __shfl_xor_sync(0xffffffffu, m0, 2));
            m1 = fmaxf(m1, __shfl_xor_sync(0xffffffffu, m1, 1));
            m1 = fmaxf(m1, __shfl_xor_sync(0xffffffffu, m1, 2));
            float nm0 = fmaxf(rmax0, m0), nm1 = fmaxf(rmax1, m1);
            float al0 = __expf(rmax0 - nm0), al1 = __expf(rmax1 - nm1);
            float ls0 = 0.f, ls1 = 0.f;
#pragma unroll
            for (int nt = 0; nt < 4; nt++) {
                s[nt][0] = __expf(s[nt][0] - nm0);
                s[nt][1] = __expf(s[nt][1] - nm0);
                s[nt][2] = __expf(s[nt][2] - nm1);
                s[nt][3] = __expf(s[nt][3] - nm1);
                ls0 += s[nt][0] + s[nt][1];
                ls1 += s[nt][2] + s[nt][3];
            }
            ls0 += __shfl_xor_sync(0xffffffffu, ls0, 1);
            ls0 += __shfl_xor_sync(0xffffffffu, ls0, 2);
            ls1 += __shfl_xor_sync(0xffffffffu, ls1, 1);
            ls1 += __shfl_xor_sync(0xffffffffu, ls1, 2);
            rsum0 = rsum0 * al0 + ls0;
            rsum1 = rsum1 * al1 + ls1;
            rmax0 = nm0; rmax1 = nm1;
#pragma unroll
            for (int nt = 0; nt < 32; nt++) {
                o[nt][0] *= al0; o[nt][1] *= al0;
                o[nt][2] *= al1; o[nt][3] *= al1;
            }
            // pack P hi/lo (fp16)
            uint32_t ph[4][2], pl[4][2];
#pragma unroll
            for (int nt = 0; nt < 4; nt++) {
                __half2 h01 = __floats2half2_rn(s[nt][0], s[nt][1]);
                __half2 h23 = __floats2half2_rn(s[nt][2], s[nt][3]);
                ph[nt][0] = *(uint32_t*)&h01;
                ph[nt][1] = *(uint32_t*)&h23;
                __half2 l01 = __floats2half2_rn(s[nt][0] - __low2float(h01),
                                                s[nt][1] - __high2float(h01));
                __half2 l23 = __floats2half2_rn(s[nt][2] - __low2float(h23),
                                                s[nt][3] - __high2float(h23));
                pl[nt][0] = *(uint32_t*)&l01;
                pl[nt][1] = *(uint32_t*)&l23;
            }
#pragma unroll
            for (int kk = 0; kk < 2; kk++) {
                uint32_t Ah[4] = {ph[2 * kk][0], ph[2 * kk][1], ph[2 * kk + 1][0], ph[2 * kk + 1][1]};
                uint32_t Al[4] = {pl[2 * kk][0], pl[2 * kk][1], pl[2 * kk + 1][0], pl[2 * kk + 1][1]};
#pragma unroll
                for (int p = 0; p < 16; p++) {
                    uint32_t rv[4];
                    LDSM4(rv, vB + p * (16 * VLD * 2) + kk * 32);
                    mma16816(o[2 * p], Ah, &rv[0]);
                    mma16816(o[2 * p], Al, &rv[0]);
                    mma16816(o[2 * p + 1], Ah, &rv[2]);
                    mma16816(o[2 * p + 1], Al, &rv[2]);
                }
            }
        }
        __syncthreads();
        if (j + 1 < ntiles) LOAD_V(kt + 32);
        CP_COMMIT();
    }

    // epilogue: normalize and write fp16 directly into A2 hi region
    float inv0 = 1.0f / rsum0, inv1 = 1.0f / rsum1;
    __half* d0p = A2out + (size_t)(b * S_ + row0) * GK2 + h * HD_;
    __half* d1p = A2out + (size_t)(b * S_ + row1) * GK2 + h * HD_;
#pragma unroll
    for (int nt = 0; nt < 32; nt++) {
        int d = nt * 8 + tcol;
        __half2 v0 = __floats2half2_rn(o[nt][0] * inv0, o[nt][1] * inv0);
        __half2 v1 = __floats2half2_rn(o[nt][2] * inv1, o[nt][3] * inv1);
        *(__half2*)(d0p + d) = v0;
        *(__half2*)(d1p + d) = v1;
    }
#undef LOAD_K
#undef LOAD_V
}

// ---------------------------------------------------------------------------
// Launch
// ---------------------------------------------------------------------------
extern "C" void kernel_launch(void* const* d_in, const int* in_sizes, int n_in,
                              void* d_out, int out_size)
{
    const float* hidden    = (const float*)d_in[0];
    const int*   positions = (const int*)d_in[1];
    const float* Wq        = (const float*)d_in[2];
    const float* bq        = (const float*)d_in[3];
    const float* Wk        = (const float*)d_in[4];
    const float* bk        = (const float*)d_in[5];
    const float* Wv        = (const float*)d_in[6];
    const float* bv        = (const float*)d_in[7];
    const float* Wo        = (const float*)d_in[8];
    float* out = (float*)d_out;

    float *qp, *kp, *vp;
    __half *a2, *w2, *q2, *k2, *vt;
    cudaGetSymbolAddress((void**)&qp, g_q);
    cudaGetSymbolAddress((void**)&kp, g_k);
    cudaGetSymbolAddress((void**)&vp, g_v);
    cudaGetSymbolAddress((void**)&a2, g_a2);
    cudaGetSymbolAddress((void**)&w2, g_w2);
    cudaGetSymbolAddress((void**)&q2, g_q2);
    cudaGetSymbolAddress((void**)&k2, g_k2);
    cudaGetSymbolAddress((void**)&vt, g_vt);

    const int M = B_ * S_;
    const size_t gemm_smem = (size_t)NSTAGE * 128 * LDS_K * 2 * 2 + 512;
    cudaFuncSetAttribute(gemm_mma, cudaFuncAttributeMaxDynamicSharedMemorySize, (int)gemm_smem);

    convA2<<<M * 512 / 256, 256>>>(hidden, a2);

    // Q projection: 2-term split-A (precision anchor for logits)
    convW2<<<dim3(2048 / 32, 64), 256>>>(Wq, w2, 2048);
    gemm_mma<<<dim3(16, 64), 256, gemm_smem>>>(a2, w2, bq, qp, 2048, 64);
    // K/V projections: single-term A (outputs are rounded to fp16 downstream anyway)
    convW2<<<dim3(1024 / 32, 64), 256>>>(Wk, w2, 1024);
    gemm_mma<<<dim3(8, 64), 256, gemm_smem>>>(a2, w2, bk, kp, 1024, 32);
    convW2<<<dim3(1024 / 32, 64), 256>>>(Wv, w2, 1024);
    gemm_mma<<<dim3(8, 64), 256, gemm_smem>>>(a2, w2, bv, vp, 1024, 32);

    conv_qk<<<(B_ * S_ * 12 * 32) / 256, 256>>>(qp, kp, positions, q2, k2);
    conv_v<<<dim3(S_ / 32, HD_ / 32, B_ * NKV_), 256>>>(vp, vt);

    // attention writes fp16 directly into A2 hi region
    {
        size_t smem = (size_t)(128 * QLD + 32 * KLD + 256 * VLD) * 2;  // 170,496 B
        cudaFuncSetAttribute(attn_mma, cudaFuncAttributeMaxDynamicSharedMemorySize, (int)smem);
        attn_mma<<<dim3(S_ / 128, NH_, B_), 256, smem>>>(q2, k2, vt, a2);
    }

    // O projection: single-term A (attention output already fp16-rounded)
    convW2<<<dim3(2048 / 32, 64), 256>>>(Wo, w2, 2048);
    gemm_mma<<<dim3(16, 64), 256, gemm_smem>>>(a2, w2, nullptr, out, 2048, 32);
}

// round 7
// speedup vs baseline: 7.8145x; 1.3243x over previous
#include <cuda_runtime.h>
#include <cuda_fp16.h>
#include <math.h>
#include <stdint.h>

// Problem constants (Gemma2 attention layer)
#define B_ 4
#define S_ 2048
#define H_ 2048
#define NH_ 8
#define NKV_ 4
#define HD_ 256
#define WIN_ 1024
#define SCALE_ 0.0625f   // 256^-0.5

#define GK_   2048       // inner K of every GEMM
#define KC    64         // K-chunk per pipeline stage
#define NC    32         // GK_ / KC
#define NSTAGE 3
#define LDS_K 72         // padded smem k-stride (fp16 elems), 144B rows

// ---------------------------------------------------------------------------
// Scratch (device globals — no allocation allowed)
// ---------------------------------------------------------------------------
__device__ float g_q[(size_t)B_ * S_ * NH_ * HD_];
__device__ float g_k[(size_t)B_ * S_ * NKV_ * HD_];
__device__ float g_v[(size_t)B_ * S_ * NKV_ * HD_];
__device__ __half g_a2[(size_t)B_ * S_ * GK_];                // 32 MB (single fp16)
__device__ __half g_w2[(size_t)H_ * GK_];                     // 8 MB (single fp16)
__device__ float2 g_rope[(size_t)B_ * S_ * 128];              // cos/sin table
// attention operands
__device__ __half g_q2[(size_t)B_ * NH_ * S_ * 256];          // [b][h][s][q(256)]
__device__ __half g_k2[(size_t)B_ * NKV_ * S_ * 256];         // [b][kvh][s][k(256)]
__device__ __half g_vt[(size_t)B_ * NKV_ * 256 * S_];         // [b][kvh][d(256)][s]

// ---------------------------------------------------------------------------
// Helpers
// ---------------------------------------------------------------------------
__device__ __forceinline__ uint32_t smem_u32(const void* p) {
    uint32_t a;
    asm("{ .reg .u64 t; cvta.to.shared.u64 t, %1; cvt.u32.u64 %0, t; }" : "=r"(a) : "l"(p));
    return a;
}
__device__ __forceinline__ void cp16(uint32_t dst, const void* src) {
    asm volatile("cp.async.cg.shared.global [%0], [%1], 16;" :: "r"(dst), "l"(src));
}
#define CP_COMMIT() asm volatile("cp.async.commit_group;" ::: "memory")
#define CP_WAIT1()  asm volatile("cp.async.wait_group 1;" ::: "memory")

__device__ __forceinline__ void mma16816(float* c, const uint32_t* a, const uint32_t* b) {
    asm volatile(
        "mma.sync.aligned.m16n8k16.row.col.f32.f16.f16.f32 "
        "{%0,%1,%2,%3}, {%4,%5,%6,%7}, {%8,%9}, {%0,%1,%2,%3};"
        : "+f"(c[0]), "+f"(c[1]), "+f"(c[2]), "+f"(c[3])
        : "r"(a[0]), "r"(a[1]), "r"(a[2]), "r"(a[3]), "r"(b[0]), "r"(b[1]));
}
#define LDSM4(r, a)                                                             \
    asm volatile("ldmatrix.sync.aligned.m8n8.x4.shared.b16 {%0,%1,%2,%3}, [%4];" \
        : "=r"((r)[0]), "=r"((r)[1]), "=r"((r)[2]), "=r"((r)[3]) : "r"(a))

// ---------------------------------------------------------------------------
// RoPE table: cos/sin per (b*s, d<128), computed once.
// ---------------------------------------------------------------------------
__global__ __launch_bounds__(256) void rope_table(const int* __restrict__ positions,
                                                  float2* __restrict__ T)
{
    int idx = blockIdx.x * 256 + threadIdx.x;     // B*S*128
    int d = idx & 127;
    int bs = idx >> 7;
    int pos = positions[bs];
    // 10000^(-d/128) = exp2(-d * log2(10000)/128)
    float inv_freq = exp2f(-(float)d * 0.103810253f);
    float fr = (float)pos * inv_freq;
    float sn, cs;
    sincosf(fr, &sn, &cs);
    T[idx] = make_float2(cs, sn);
}

// ---------------------------------------------------------------------------
// Conversions for GEMM
// ---------------------------------------------------------------------------
__global__ __launch_bounds__(256) void convA2(const float* __restrict__ A,
                                              __half* __restrict__ A2)
{
    int idx = blockIdx.x * 256 + threadIdx.x;
    int m = idx >> 9;
    int j = (idx & 511) * 4;
    float4 v = *(const float4*)(A + (size_t)m * GK_ + j);
    __half h[4] = {__float2half_rn(v.x), __float2half_rn(v.y),
                   __float2half_rn(v.z), __float2half_rn(v.w)};
    *(uint2*)&A2[(size_t)m * GK_ + j] = *(uint2*)h;
}

__global__ __launch_bounds__(256) void convW2(const float* __restrict__ W,
                                              __half* __restrict__ W2, int N)
{
    __shared__ float t[32][33];
    int n0 = blockIdx.x * 32, k0 = blockIdx.y * 32;
    int tx = threadIdx.x & 31, ty = threadIdx.x >> 5;
#pragma unroll
    for (int i = 0; i < 32; i += 8)
        t[ty + i][tx] = W[(size_t)(k0 + ty + i) * N + n0 + tx];
    __syncthreads();
#pragma unroll
    for (int i = 0; i < 32; i += 8) {
        int n = n0 + ty + i, k = k0 + tx;
        W2[(size_t)n * GK_ + k] = __float2half_rn(t[tx][ty + i]);
    }
}

// ---------------------------------------------------------------------------
// mma.sync fp16 GEMM: C[8192,Nn] = A2[8192,2048] @ W2[Nn,2048]^T + bias
// ---------------------------------------------------------------------------
__global__ __launch_bounds__(256) void gemm_mma(
    const __half* __restrict__ A2, const __half* __restrict__ B2,
    const float* __restrict__ bias, float* __restrict__ C, int Nn)
{
    extern __shared__ __align__(16) char smraw[];
    __half* sA = (__half*)smraw;
    __half* sB = sA + NSTAGE * 128 * LDS_K;
    float* sbias = (float*)(sB + NSTAGE * 128 * LDS_K);

    const int tid = threadIdx.x;
    const int m0 = blockIdx.y * 128;
    const int n0 = blockIdx.x * 128;

    if (tid < 128) sbias[tid] = bias ? bias[n0 + tid] : 0.f;

    const int seg = tid & 7;
    const int r0  = tid >> 3;
    const __half* Ag = A2 + (size_t)m0 * GK_ + seg * 8;
    const __half* Bg = B2 + (size_t)n0 * GK_ + seg * 8;
    const uint32_t sAu = smem_u32(sA);
    const uint32_t sBu = smem_u32(sB);

#define LOAD_STAGE(chunk, st) do {                                              \
    int _k0 = (chunk) * KC;                                                     \
    uint32_t _da = sAu + (uint32_t)(st) * 18432;                                \
    uint32_t _db = sBu + (uint32_t)(st) * 18432;                                \
    _Pragma("unroll")                                                           \
    for (int _rr = 0; _rr < 4; _rr++) {                                         \
        int _row = r0 + _rr * 32;                                               \
        uint32_t _o = (uint32_t)(_row * LDS_K + seg * 8) * 2;                   \
        cp16(_da + _o, Ag + (size_t)_row * GK_ + _k0);                          \
        cp16(_db + _o, Bg + (size_t)_row * GK_ + _k0);                          \
    }                                                                           \
} while (0)

    const int wid = tid >> 5, lane = tid & 31;
    const int wm = (wid >> 2) * 64;
    const int wn = (wid & 3) * 32;
    const int g = lane >> 2, t = lane & 3;

    const uint32_t aOff = (uint32_t)((wm + (lane & 15)) * 144 + (lane >> 4) * 16);
    const uint32_t bOff = (uint32_t)((wn + ((lane >> 4) << 3) + (lane & 7)) * 144 +
                                     ((lane >> 3) & 1) * 16);

    float acc[4][4][4];
#pragma unroll
    for (int mi = 0; mi < 4; mi++)
#pragma unroll
        for (int ni = 0; ni < 4; ni++)
#pragma unroll
            for (int e = 0; e < 4; e++) acc[mi][ni][e] = 0.f;

    LOAD_STAGE(0, 0); CP_COMMIT();
    LOAD_STAGE(1, 1); CP_COMMIT();

    for (int c = 0; c < NC; c++) {
        CP_WAIT1();
        __syncthreads();

        int lc = c + 2;
        int st_ld = lc - (lc / 3) * 3;
        if (lc < NC) LOAD_STAGE(lc, st_ld);
        CP_COMMIT();

        int st = c - (c / 3) * 3;
        const uint32_t aS = sAu + st * 18432 + aOff;
        const uint32_t bS = sBu + st * 18432 + bOff;

#pragma unroll
        for (int ks = 0; ks < 4; ks++) {
            uint32_t af[4][4], bq[2][4];
#pragma unroll
            for (int mi = 0; mi < 4; mi++) LDSM4(af[mi], aS + mi * 2304 + ks * 32);
#pragma unroll
            for (int p = 0; p < 2; p++) LDSM4(bq[p], bS + p * 2304 + ks * 32);
#pragma unroll
            for (int mi = 0; mi < 4; mi++)
#pragma unroll
                for (int ni = 0; ni < 4; ni++)
                    mma16816(acc[mi][ni], af[mi], &bq[ni >> 1][(ni & 1) * 2]);
        }
    }

    __syncthreads();
#pragma unroll
    for (int mi = 0; mi < 4; mi++) {
        int row = m0 + wm + mi * 16 + g;
#pragma unroll
        for (int ni = 0; ni < 4; ni++) {
            int lcol = wn + ni * 8 + 2 * t;
            float b0 = sbias[lcol], b1 = sbias[lcol + 1];
            float2 v0 = {acc[mi][ni][0] + b0, acc[mi][ni][1] + b1};
            float2 v1 = {acc[mi][ni][2] + b0, acc[mi][ni][3] + b1};
            *(float2*)(C + (size_t)row * Nn + n0 + lcol) = v0;
            *(float2*)(C + (size_t)(row + 8) * Nn + n0 + lcol) = v1;
        }
    }
#undef LOAD_STAGE
}

// ---------------------------------------------------------------------------
// Fused RoPE (table) + scale + fp16 conversion for Q and K (single fp16 each).
// ---------------------------------------------------------------------------
__global__ __launch_bounds__(256) void conv_qk(
    const float* __restrict__ q, const float* __restrict__ k,
    const float2* __restrict__ T,
    __half* __restrict__ Q2, __half* __restrict__ K2)
{
    int idx = blockIdx.x * 256 + threadIdx.x;   // 4*2048*12*32
    int dg = idx & 31;
    int r = idx >> 5;
    int head = r % 12;
    int bs = r / 12;
    int b = bs >> 11, s = bs & 2047;
    int d0 = dg * 4;

    const bool isq = head < NH_;
    const float* src;
    float sc;
    if (isq) {
        src = q + ((size_t)bs * NH_ + head) * HD_;
        sc = SCALE_;
    } else {
        src = k + ((size_t)bs * NKV_ + (head - NH_)) * HD_;
        sc = 1.0f;
    }
    float4 x1 = *(const float4*)(src + d0);
    float4 x2 = *(const float4*)(src + d0 + 128);
    float a1[4] = {x1.x, x1.y, x1.z, x1.w};
    float a2[4] = {x2.x, x2.y, x2.z, x2.w};
    __half h1[4], h2[4];
#pragma unroll
    for (int e = 0; e < 4; e++) {
        float2 cssn = T[(size_t)bs * 128 + d0 + e];
        float y1 = (a1[e] * cssn.x - a2[e] * cssn.y) * sc;
        float y2 = (a2[e] * cssn.x + a1[e] * cssn.y) * sc;
        h1[e] = __float2half_rn(y1);
        h2[e] = __float2half_rn(y2);
    }
    __half* dst = isq ? (Q2 + ((size_t)(b * NH_ + head) * S_ + s) * 256)
                      : (K2 + ((size_t)(b * NKV_ + head - NH_) * S_ + s) * 256);
    *(uint2*)(dst + d0)       = *(uint2*)h1;
    *(uint2*)(dst + 128 + d0) = *(uint2*)h2;
}

// ---------------------------------------------------------------------------
// V transpose + single fp16: g_v [b][s][kvh][256] -> g_vt [b][kvh][256][S]
// ---------------------------------------------------------------------------
__global__ __launch_bounds__(256) void conv_v(const float* __restrict__ v,
                                              __half* __restrict__ Vt)
{
    __shared__ float tile[32][33];
    int s0 = blockIdx.x * 32, d0 = blockIdx.y * 32;
    int b = blockIdx.z >> 2, kvh = blockIdx.z & 3;
    int tx = threadIdx.x & 31, ty = threadIdx.x >> 5;
#pragma unroll
    for (int i = 0; i < 32; i += 8)
        tile[ty + i][tx] = v[((size_t)(b * S_ + s0 + ty + i) * NKV_ + kvh) * HD_ + d0 + tx];
    __syncthreads();
    size_t base = (size_t)(b * NKV_ + kvh) * 256;
#pragma unroll
    for (int i = 0; i < 32; i += 8) {
        int d = d0 + ty + i;
        Vt[(base + d) * S_ + s0 + tx] = __float2half_rn(tile[tx][ty + i]);
    }
}

// ---------------------------------------------------------------------------
// Tensor-core sliding-window flash attention (fp16).
// QK: single pass. PV: 2 mmas (ph*v + pl*v).
// Epilogue writes fp16 directly into A2 for the O projection.
// ---------------------------------------------------------------------------
#define QLD 264      // fp16 elems per Q smem row (256 + 8 pad)
#define KLD 264      // fp16 elems per K smem row (256 + 8 pad)
#define VLD 40       // fp16 elems per V smem row (32 + 8 pad)

__global__ __launch_bounds__(256, 1) void attn_mma(
    const __half* __restrict__ Q2, const __half* __restrict__ K2,
    const __half* __restrict__ Vt, __half* __restrict__ A2out)
{
    extern __shared__ __align__(16) __half smb[];
    __half* Qs = smb;                 // [128][264]
    __half* Ks = Qs + 128 * QLD;      // [32][264]
    __half* Vs = Ks + 32 * KLD;       // [256][40]

    const int tid = threadIdx.x;
    const int w = tid >> 5, lane = tid & 31;
    const int g = lane >> 2, t = lane & 3;
    const int q0 = blockIdx.x * 128;
    const int h = blockIdx.y;
    const int b = blockIdx.z;
    const int kvh = h >> 1;

    const uint32_t QsA = smem_u32(Qs);
    const uint32_t KsA = smem_u32(Ks);
    const uint32_t VsA = smem_u32(Vs);

    const __half* Qg = Q2 + ((size_t)(b * NH_ + h) * S_ + q0) * 256;
    const __half* Kg = K2 + (size_t)(b * NKV_ + kvh) * S_ * 256;
    const __half* Vg = Vt + (size_t)(b * NKV_ + kvh) * 256 * S_;

    const uint32_t qA = QsA + (uint32_t)((w * 16 + (lane & 15)) * QLD * 2 + (lane >> 4) * 16);
    const uint32_t kB = KsA + (uint32_t)((((lane >> 4) << 3) + (lane & 7)) * KLD * 2 +
                                         ((lane >> 3) & 1) * 16);
    const uint32_t vB = VsA + (uint32_t)((((lane >> 4) << 3) + (lane & 7)) * VLD * 2 +
                                         ((lane >> 3) & 1) * 16);

    // ---- load Q tile: 128 rows x 256 elems
#pragma unroll
    for (int it = 0; it < 16; it++) {
        int idx = tid + it * 256;
        int r = idx >> 5, seg = idx & 31;
        cp16(QsA + (uint32_t)(r * QLD + seg * 8) * 2, Qg + (size_t)r * 256 + seg * 8);
    }
    CP_COMMIT();

    int lo = q0 - (WIN_ - 1); if (lo < 0) lo = 0;
    const int kt0 = (lo >> 5) << 5;
    const int ntiles = ((q0 + 96) - kt0) / 32 + 1;

#define LOAD_K(kt) do {                                                         \
    _Pragma("unroll")                                                           \
    for (int _it = 0; _it < 4; _it++) {                                         \
        int _i = tid + _it * 256;                                               \
        int _r = _i >> 5, _sg = _i & 31;                                        \
        cp16(KsA + (uint32_t)(_r * KLD + _sg * 8) * 2,                          \
             Kg + ((size_t)((kt) + _r)) * 256 + _sg * 8);                       \
    }                                                                           \
} while (0)
#define LOAD_V(kt) do {                                                         \
    _Pragma("unroll")                                                           \
    for (int _it = 0; _it < 4; _it++) {                                         \
        int _i = tid + _it * 256;                                               \
        int _r = _i >> 2, _sg = _i & 3;                                         \
        cp16(VsA + (uint32_t)(_r * VLD + _sg * 8) * 2,                          \
             Vg + (size_t)_r * S_ + (kt) + _sg * 8);                            \
    }                                                                           \
} while (0)

    LOAD_K(kt0); CP_COMMIT();
    LOAD_V(kt0); CP_COMMIT();

    float o[32][4];
#pragma unroll
    for (int nt = 0; nt < 32; nt++)
#pragma unroll
        for (int e = 0; e < 4; e++) o[nt][e] = 0.f;
    float rmax0 = -1e20f, rmax1 = -1e20f, rsum0 = 0.f, rsum1 = 0.f;

    const int rmin = q0 + w * 16;
    const int rmax_w = rmin + 15;
    const int row0 = rmin + g;
    const int row1 = row0 + 8;
    const int tcol = 2 * t;

    for (int j = 0; j < ntiles; j++) {
        const int kt = kt0 + 32 * j;
        const bool skipT = (kt > rmax_w) || (kt + 31 < rmin - (WIN_ - 1));
        const bool edge = !((kt + 31 <= rmin) && (kt >= rmax_w - (WIN_ - 1)));

        CP_WAIT1();
        __syncthreads();

        float s[4][4];
        if (!skipT) {
#pragma unroll
            for (int nt = 0; nt < 4; nt++)
#pragma unroll
                for (int e = 0; e < 4; e++) s[nt][e] = 0.f;
#pragma unroll 4
            for (int ks = 0; ks < 16; ks++) {
                uint32_t a[4], b0[4], b1[4];
                LDSM4(a, qA + ks * 32);
                LDSM4(b0, kB + ks * 32);
                LDSM4(b1, kB + 16 * KLD * 2 + ks * 32);
                mma16816(s[0], a, &b0[0]);
                mma16816(s[1], a, &b0[2]);
                mma16816(s[2], a, &b1[0]);
                mma16816(s[3], a, &b1[2]);
            }
        }
        __syncthreads();
        if (j + 1 < ntiles) LOAD_K(kt + 32);
        CP_COMMIT();
        CP_WAIT1();
        __syncthreads();

        if (!skipT) {
            if (edge) {
#pragma unroll
                for (int nt = 0; nt < 4; nt++) {
                    int c0 = kt + nt * 8 + tcol, c1 = c0 + 1;
                    if (!(c0 <= row0 && c0 > row0 - WIN_)) s[nt][0] = -1e30f;
                    if (!(c1 <= row0 && c1 > row0 - WIN_)) s[nt][1] = -1e30f;
                    if (!(c0 <= row1 && c0 > row1 - WIN_)) s[nt][2] = -1e30f;
                    if (!(c1 <= row1 && c1 > row1 - WIN_)) s[nt][3] = -1e30f;
                }
            }
            float m0 = fmaxf(fmaxf(s[0][0], s[0][1]), fmaxf(s[1][0], s[1][1]));
            m0 = fmaxf(m0, fmaxf(fmaxf(s[2][0], s[2][1]), fmaxf(s[3][0], s[3][1])));
            float m1 = fmaxf(fmaxf(s[0][2], s[0][3]), fmaxf(s[1][2], s[1][3]));
            m1 = fmaxf(m1, fmaxf(fmaxf(s[2][2], s[2][3]), fmaxf(s[3][2], s[3][3])));
            m0 = fmaxf(m0, __shfl_xor_sync(0xffffffffu, m0, 1));
            m0 = fmaxf(m0, __shfl_xor_sync(0xffffffffu, m0, 2));
            m1 = fmaxf(m1, __shfl_xor_sync(0xffffffffu, m1, 1));
            m1 = fmaxf(m1, __shfl_xor_sync(0xffffffffu, m1, 2));
            float nm0 = fmaxf(rmax0, m0), nm1 = fmaxf(rmax1, m1);
            float al0 = __expf(rmax0 - nm0), al1 = __expf(rmax1 - nm1);
            float ls0 = 0.f, ls1 = 0.f;
#pragma unroll
            for (int nt = 0; nt < 4; nt++) {
                s[nt][0] = __expf(s[nt][0] - nm0);
                s[nt][1] = __expf(s[nt][1] - nm0);
                s[nt][2] = __expf(s[nt][2] - nm1);
                s[nt][3] = __expf(s[nt][3] - nm1);
                ls0 += s[nt][0] + s[nt][1];
                ls1 += s[nt][2] + s[nt][3];
            }
            ls0 += __shfl_xor_sync(0xffffffffu, ls0, 1);
            ls0 += __shfl_xor_sync(0xffffffffu, ls0, 2);
            ls1 += __shfl_xor_sync(0xffffffffu, ls1, 1);
            ls1 += __shfl_xor_sync(0xffffffffu, ls1, 2);
            rsum0 = rsum0 * al0 + ls0;
            rsum1 = rsum1 * al1 + ls1;
            rmax0 = nm0; rmax1 = nm1;
#pragma unroll
            for (int nt = 0; nt < 32; nt++) {
                o[nt][0] *= al0; o[nt][1] *= al0;
                o[nt][2] *= al1; o[nt][3] *= al1;
            }
            // pack P hi/lo (fp16)
            uint32_t ph[4][2], pl[4][2];
#pragma unroll
            for (int nt = 0; nt < 4; nt++) {
                __half2 h01 = __floats2half2_rn(s[nt][0], s[nt][1]);
                __half2 h23 = __floats2half2_rn(s[nt][2], s[nt][3]);
                ph[nt][0] = *(uint32_t*)&h01;
                ph[nt][1] = *(uint32_t*)&h23;
                __half2 l01 = __floats2half2_rn(s[nt][0] - __low2float(h01),
                                                s[nt][1] - __high2float(h01));
                __half2 l23 = __floats2half2_rn(s[nt][2] - __low2float(h23),
                                                s[nt][3] - __high2float(h23));
                pl[nt][0] = *(uint32_t*)&l01;
                pl[nt][1] = *(uint32_t*)&l23;
            }
#pragma unroll
            for (int kk = 0; kk < 2; kk++) {
                uint32_t Ah[4] = {ph[2 * kk][0], ph[2 * kk][1], ph[2 * kk + 1][0], ph[2 * kk + 1][1]};
                uint32_t Al[4] = {pl[2 * kk][0], pl[2 * kk][1], pl[2 * kk + 1][0], pl[2 * kk + 1][1]};
#pragma unroll
                for (int p = 0; p < 16; p++) {
                    uint32_t rv[4];
                    LDSM4(rv, vB + p * (16 * VLD * 2) + kk * 32);
                    mma16816(o[2 * p], Ah, &rv[0]);
                    mma16816(o[2 * p], Al, &rv[0]);
                    mma16816(o[2 * p + 1], Ah, &rv[2]);
                    mma16816(o[2 * p + 1], Al, &rv[2]);
                }
            }
        }
        __syncthreads();
        if (j + 1 < ntiles) LOAD_V(kt + 32);
        CP_COMMIT();
    }

    // epilogue: normalize and write fp16 directly into A2
    float inv0 = 1.0f / rsum0, inv1 = 1.0f / rsum1;
    __half* d0p = A2out + (size_t)(b * S_ + row0) * GK_ + h * HD_;
    __half* d1p = A2out + (size_t)(b * S_ + row1) * GK_ + h * HD_;
#pragma unroll
    for (int nt = 0; nt < 32; nt++) {
        int d = nt * 8 + tcol;
        __half2 v0 = __floats2half2_rn(o[nt][0] * inv0, o[nt][1] * inv0);
        __half2 v1 = __floats2half2_rn(o[nt][2] * inv1, o[nt][3] * inv1);
        *(__half2*)(d0p + d) = v0;
        *(__half2*)(d1p + d) = v1;
    }
#undef LOAD_K
#undef LOAD_V
}

// ---------------------------------------------------------------------------
// Launch
// ---------------------------------------------------------------------------
extern "C" void kernel_launch(void* const* d_in, const int* in_sizes, int n_in,
                              void* d_out, int out_size)
{
    const float* hidden    = (const float*)d_in[0];
    const int*   positions = (const int*)d_in[1];
    const float* Wq        = (const float*)d_in[2];
    const float* bq        = (const float*)d_in[3];
    const float* Wk        = (const float*)d_in[4];
    const float* bk        = (const float*)d_in[5];
    const float* Wv        = (const float*)d_in[6];
    const float* bv        = (const float*)d_in[7];
    const float* Wo        = (const float*)d_in[8];
    float* out = (float*)d_out;

    float *qp, *kp, *vp;
    float2* rt;
    __half *a2, *w2, *q2, *k2, *vt;
    cudaGetSymbolAddress((void**)&qp, g_q);
    cudaGetSymbolAddress((void**)&kp, g_k);
    cudaGetSymbolAddress((void**)&vp, g_v);
    cudaGetSymbolAddress((void**)&a2, g_a2);
    cudaGetSymbolAddress((void**)&w2, g_w2);
    cudaGetSymbolAddress((void**)&rt, g_rope);
    cudaGetSymbolAddress((void**)&q2, g_q2);
    cudaGetSymbolAddress((void**)&k2, g_k2);
    cudaGetSymbolAddress((void**)&vt, g_vt);

    const int M = B_ * S_;
    const size_t gemm_smem = (size_t)NSTAGE * 128 * LDS_K * 2 * 2 + 512;
    cudaFuncSetAttribute(gemm_mma, cudaFuncAttributeMaxDynamicSharedMemorySize, (int)gemm_smem);

    rope_table<<<(B_ * S_ * 128) / 256, 256>>>(positions, rt);
    convA2<<<M * 512 / 256, 256>>>(hidden, a2);

    convW2<<<dim3(2048 / 32, 64), 256>>>(Wq, w2, 2048);
    gemm_mma<<<dim3(16, 64), 256, gemm_smem>>>(a2, w2, bq, qp, 2048);
    convW2<<<dim3(1024 / 32, 64), 256>>>(Wk, w2, 1024);
    gemm_mma<<<dim3(8, 64), 256, gemm_smem>>>(a2, w2, bk, kp, 1024);
    convW2<<<dim3(1024 / 32, 64), 256>>>(Wv, w2, 1024);
    gemm_mma<<<dim3(8, 64), 256, gemm_smem>>>(a2, w2, bv, vp, 1024);

    conv_qk<<<(B_ * S_ * 12 * 32) / 256, 256>>>(qp, kp, rt, q2, k2);
    conv_v<<<dim3(S_ / 32, HD_ / 32, B_ * NKV_), 256>>>(vp, vt);

    // attention writes fp16 directly into A2
    {
        size_t smem = (size_t)(128 * QLD + 32 * KLD + 256 * VLD) * 2;  // 104,960 B
        cudaFuncSetAttribute(attn_mma, cudaFuncAttributeMaxDynamicSharedMemorySize, (int)smem);
        attn_mma<<<dim3(S_ / 128, NH_, B_), 256, smem>>>(q2, k2, vt, a2);
    }

    // O projection
    convW2<<<dim3(2048 / 32, 64), 256>>>(Wo, w2, 2048);
    gemm_mma<<<dim3(16, 64), 256, gemm_smem>>>(a2, w2, nullptr, out, 2048);
}